// round 1
// baseline (speedup 1.0000x reference)
#include <cuda_runtime.h>
#include <math.h>

// Problem constants
#define Bd   2
#define Cd   128
#define Hd   256
#define Wdm  256
#define HW   65536          // Hd*Wdm
#define GR   320            // padded rows of stacked GEMM output (288 used)
#define EPSV 1e-5

// Scratch (device globals: allocation-free kernel_launch)
__device__ float  d_Wg[GR * 128];            // stacked weights [GR][128]
__device__ float  d_cA[128];
__device__ float  d_cB[128];
__device__ float  d_G[(size_t)Bd * GR * HW]; // GEMM output: z(0..127) y(128..255) u(256..271) t(272..287)
__device__ float  d_nn[(size_t)Bd * Cd * HW];
__device__ double d_part[4096 * 2];          // per-block (sum, sumsq)
__device__ float  d_stats[4];                // mu0, rsig0, mu1, rsig1

// ---------------------------------------------------------------------------
// Prep: build stacked weight matrix Wg and folded biases cA, cB.
// rows 0..127   : A = Wu[:, :128] @ Wn
// rows 128..255 : B = Wu[:, 128:] @ We
// rows 256..271 : Wa1[:, :128]   (u weights)
// rows 272..287 : Wa1[:, 128:]   (t weights)
// rows 288..319 : zero pad
// block 320     : cA[o] = Wu[o,:128]·bn + bu[o],  cB[o] = Wu[o,128:]·be
// ---------------------------------------------------------------------------
__global__ void prep_kernel(const float* __restrict__ Wn, const float* __restrict__ We,
                            const float* __restrict__ Wa1, const float* __restrict__ Wu,
                            const float* __restrict__ bn, const float* __restrict__ be,
                            const float* __restrict__ bu) {
    __shared__ float wbuf[128];
    const int r = blockIdx.x;
    const int c = threadIdx.x;  // 0..127
    if (r < GR) {
        float v = 0.f;
        if (r < 128) {
            wbuf[c] = Wu[r * 256 + c];
            __syncthreads();
            #pragma unroll 8
            for (int k = 0; k < 128; k++) v += wbuf[k] * Wn[k * 128 + c];
        } else if (r < 256) {
            wbuf[c] = Wu[(r - 128) * 256 + 128 + c];
            __syncthreads();
            #pragma unroll 8
            for (int k = 0; k < 128; k++) v += wbuf[k] * We[k * 128 + c];
        } else if (r < 272) {
            v = Wa1[(r - 256) * 256 + c];
        } else if (r < 288) {
            v = Wa1[(r - 272) * 256 + 128 + c];
        }
        d_Wg[r * 128 + c] = v;
    } else {
        float a = bu[c], bb = 0.f;
        for (int k = 0; k < 128; k++) {
            a  += Wu[c * 256 + k]       * bn[k];
            bb += Wu[c * 256 + 128 + k] * be[k];
        }
        d_cA[c] = a;
        d_cB[c] = bb;
    }
}

// ---------------------------------------------------------------------------
// Stacked GEMM:  G[b][m][p] = sum_k Wg[m][k] * x[b][k][p]
// M = 320 (padded), K = 128, N = 65536 per batch.
// BM=64 BN=64 BK=32, 256 threads, 4x4 micro-tile.
// ---------------------------------------------------------------------------
__global__ void __launch_bounds__(256) gemm_kernel(const float* __restrict__ x) {
    const int b  = blockIdx.z;
    const int m0 = blockIdx.y * 64;
    const int n0 = blockIdx.x * 64;
    const float* __restrict__ X = x + (size_t)b * Cd * HW;
    float* __restrict__ G = d_G + (size_t)b * GR * HW;

    __shared__ float As[64][33];   // [m][k], padded (conflict-free store)
    __shared__ float Xs[32][64];   // [k][n]

    const int tid = threadIdx.x;
    const int tx = tid & 15, ty = tid >> 4;
    float acc[4][4] = {};

    for (int k0 = 0; k0 < 128; k0 += 32) {
        {   // A tile: 64 rows x 32 k
            const int r = tid >> 2, kq = tid & 3;
            const float* src = d_Wg + (m0 + r) * 128 + k0 + kq * 8;
            float4 v0 = *(const float4*)(src);
            float4 v1 = *(const float4*)(src + 4);
            float* dst = &As[r][kq * 8];
            dst[0] = v0.x; dst[1] = v0.y; dst[2] = v0.z; dst[3] = v0.w;
            dst[4] = v1.x; dst[5] = v1.y; dst[6] = v1.z; dst[7] = v1.w;
        }
        {   // X tile: 32 k x 64 n
            const int kk = tid >> 3, nq = tid & 7;
            const float4* src = (const float4*)(X + (size_t)(k0 + kk) * HW + n0 + nq * 8);
            float4 v0 = src[0], v1 = src[1];
            float4* dst = (float4*)&Xs[kk][nq * 8];
            dst[0] = v0; dst[1] = v1;
        }
        __syncthreads();
        #pragma unroll
        for (int k = 0; k < 32; k++) {
            const float4 bq = *(const float4*)&Xs[k][tx * 4];
            #pragma unroll
            for (int i = 0; i < 4; i++) {
                const float a = As[ty * 4 + i][k];
                acc[i][0] += a * bq.x; acc[i][1] += a * bq.y;
                acc[i][2] += a * bq.z; acc[i][3] += a * bq.w;
            }
        }
        __syncthreads();
    }
    #pragma unroll
    for (int i = 0; i < 4; i++) {
        float4 v = make_float4(acc[i][0], acc[i][1], acc[i][2], acc[i][3]);
        *(float4*)(G + (size_t)(m0 + ty * 4 + i) * HW + n0 + tx * 4) = v;
    }
}

// ---------------------------------------------------------------------------
// Combine: per pixel, compute 4 attention gates + gather gated neighbor y,
// produce new_nodes (pre-norm) and per-block partial sums for GroupNorm.
// Block = 32 consecutive pixels (one row segment), 256 threads.
// ---------------------------------------------------------------------------
__global__ void __launch_bounds__(256) combine_kernel(const float* __restrict__ ba1,
                                                      const float* __restrict__ Wa2,
                                                      const float* __restrict__ ba2) {
    const int blk = blockIdx.x;        // 0..4095
    const int b   = blk >> 11;         // 2048 blocks/batch
    const int p0  = (blk & 2047) << 5; // pixel offset in image
    const float* __restrict__ G = d_G + (size_t)b * GR * HW;
    float* __restrict__ nn = d_nn + (size_t)b * Cd * HW;

    __shared__ float a_s[4][32];
    __shared__ float cA_s[128], cB_s[128];
    __shared__ float red[256];

    const int tid = threadIdx.x;
    if (tid < 128) { cA_s[tid] = d_cA[tid]; cB_s[tid] = d_cB[tid]; }

    const int hrow = p0 >> 8;   // all 32 pixels share the row

    // --- attention gates: threads 0..127 = (dir, px) ---
    if (tid < 128) {
        const int dir = tid >> 5, px = tid & 31;
        const int p = p0 + px, w = p & 255;
        int off; bool valid;
        switch (dir) {
            case 0:  off = -256; valid = (hrow > 0);   break;  // up    neighbor (h-1)
            case 1:  off =  256; valid = (hrow < 255); break;  // down  neighbor (h+1)
            case 2:  off =   -1; valid = (w > 0);      break;  // left  neighbor (w-1)
            default: off =    1; valid = (w < 255);    break;  // right neighbor (w+1)
        }
        float a = 0.f;
        if (valid) {
            float logit = ba2[0];
            const float* Gu = G + 256 * HW + p;
            const float* Gt = G + 272 * HW + p + off;
            #pragma unroll
            for (int i = 0; i < 16; i++) {
                float hv = Gu[i * HW] + Gt[i * HW] + ba1[i];
                hv = hv > 0.f ? hv : 0.2f * hv;          // leaky_relu(0.2)
                logit += Wa2[i] * hv;
            }
            a = 1.f / (1.f + expf(-logit));
        }
        a_s[dir][px] = a;
    }
    __syncthreads();

    // --- gated aggregation: warp w handles 16 channels, lane = pixel ---
    const int wq = tid >> 5, lane = tid & 31;
    const int p = p0 + lane;
    const float au = a_s[0][lane], ad = a_s[1][lane];
    const float al = a_s[2][lane], ar = a_s[3][lane];

    float lsum = 0.f, lsq = 0.f;
    #pragma unroll
    for (int ci = 0; ci < 16; ci++) {
        const int c = (wq << 4) + ci;
        const float* z = G + (size_t)c * HW;
        const float* y = G + (size_t)(128 + c) * HW;
        const float cb = cB_s[c];
        // invalid-direction gates are exactly 0, and all offset reads stay
        // inside this batch's G slab, so no guards needed on the loads.
        float v = z[p] + cA_s[c]
                + au * (y[p - 256] + cb) + ad * (y[p + 256] + cb)
                + al * (y[p - 1]   + cb) + ar * (y[p + 1]   + cb);
        nn[(size_t)c * HW + p] = v;
        lsum += v; lsq += v * v;
    }

    // deterministic block reduction (fixed pairing order)
    red[tid] = lsum; __syncthreads();
    for (int s = 128; s > 0; s >>= 1) { if (tid < s) red[tid] += red[tid + s]; __syncthreads(); }
    if (tid == 0) d_part[blk * 2] = (double)red[0];
    __syncthreads();
    red[tid] = lsq; __syncthreads();
    for (int s = 128; s > 0; s >>= 1) { if (tid < s) red[tid] += red[tid + s]; __syncthreads(); }
    if (tid == 0) d_part[blk * 2 + 1] = (double)red[0];
}

// ---------------------------------------------------------------------------
// Finalize GroupNorm stats per batch (deterministic, double precision).
// ---------------------------------------------------------------------------
__global__ void finalize_kernel() {
    const int b = blockIdx.x;
    __shared__ double rs[256], rq[256];
    double s = 0.0, q = 0.0;
    for (int i = threadIdx.x; i < 2048; i += 256) {
        s += d_part[(b * 2048 + i) * 2];
        q += d_part[(b * 2048 + i) * 2 + 1];
    }
    rs[threadIdx.x] = s; rq[threadIdx.x] = q; __syncthreads();
    for (int st = 128; st > 0; st >>= 1) {
        if (threadIdx.x < st) { rs[threadIdx.x] += rs[threadIdx.x + st]; rq[threadIdx.x] += rq[threadIdx.x + st]; }
        __syncthreads();
    }
    if (threadIdx.x == 0) {
        const double N = (double)Cd * HW;
        const double mu = rs[0] / N;
        const double var = rq[0] / N - mu * mu;
        d_stats[b * 2]     = (float)mu;
        d_stats[b * 2 + 1] = (float)rsqrt(var + EPSV);
    }
}

// ---------------------------------------------------------------------------
// Epilogue: out = relu((nn - mu)*rsig*gamma + beta) + x   (float4 streams)
// ---------------------------------------------------------------------------
__global__ void __launch_bounds__(256) final_kernel(const float* __restrict__ x,
                                                    const float* __restrict__ gamma,
                                                    const float* __restrict__ beta,
                                                    float* __restrict__ out) {
    const int idx4 = blockIdx.x * blockDim.x + threadIdx.x;  // 0 .. 4194303
    const int b = idx4 >> 21;           // 2^21 float4 per batch
    const int c = (idx4 >> 14) & 127;   // HW/4 = 2^14 float4 per channel
    const float mu = d_stats[b * 2], rs = d_stats[b * 2 + 1];
    const float g  = gamma[c] * rs;
    const float bt = beta[c] - mu * g;
    const float4 v  = ((const float4*)d_nn)[idx4];
    const float4 xv = ((const float4*)x)[idx4];
    float4 o;
    o.x = fmaxf(v.x * g + bt, 0.f) + xv.x;
    o.y = fmaxf(v.y * g + bt, 0.f) + xv.y;
    o.z = fmaxf(v.z * g + bt, 0.f) + xv.z;
    o.w = fmaxf(v.w * g + bt, 0.f) + xv.w;
    ((float4*)out)[idx4] = o;
}

// ---------------------------------------------------------------------------
// Launch
// inputs: 0 x, 1 Wn, 2 bn, 3 We, 4 be, 5 Wa1, 6 ba1, 7 Wa2, 8 ba2,
//         9 Wu, 10 bu, 11 gamma, 12 beta
// ---------------------------------------------------------------------------
extern "C" void kernel_launch(void* const* d_in, const int* in_sizes, int n_in,
                              void* d_out, int out_size) {
    const float* x     = (const float*)d_in[0];
    const float* Wn    = (const float*)d_in[1];
    const float* bn    = (const float*)d_in[2];
    const float* We    = (const float*)d_in[3];
    const float* be    = (const float*)d_in[4];
    const float* Wa1   = (const float*)d_in[5];
    const float* ba1   = (const float*)d_in[6];
    const float* Wa2   = (const float*)d_in[7];
    const float* ba2   = (const float*)d_in[8];
    const float* Wu    = (const float*)d_in[9];
    const float* bu    = (const float*)d_in[10];
    const float* gamma = (const float*)d_in[11];
    const float* beta  = (const float*)d_in[12];
    float* out = (float*)d_out;

    prep_kernel<<<GR + 1, 128>>>(Wn, We, Wa1, Wu, bn, be, bu);
    gemm_kernel<<<dim3(HW / 64, GR / 64, Bd), 256>>>(x);
    combine_kernel<<<4096, 256>>>(ba1, Wa2, ba2);
    finalize_kernel<<<2, 256>>>();
    final_kernel<<<(Bd * Cd * HW / 4) / 256, 256>>>(x, gamma, beta, out);
}

// round 4
// speedup vs baseline: 1.3138x; 1.3138x over previous
#include <cuda_runtime.h>
#include <cuda_bf16.h>
#include <math.h>
#include <stdint.h>

// Problem constants
#define Bd   2
#define Cd   128
#define HW   65536          // 256*256
#define GR   320            // stacked M (z 0..127, y 128..255, u 256..271, t 272..287, pad..319)
#define GUSE 288            // rows actually stored/used
#define EPSV 1e-5

// ---------------------------------------------------------------------------
// Scratch (device globals: allocation-free kernel_launch)
// ---------------------------------------------------------------------------
__device__ __nv_bfloat16 d_Whi[GR * 128];
__device__ __nv_bfloat16 d_Wlo[GR * 128];
__device__ float  d_cA[128];
__device__ float  d_cB[128];
__device__ float  d_G[(size_t)Bd * GR * HW];
__device__ float  d_nn[(size_t)Bd * Cd * HW];
__device__ double d_part[4096 * 2];
__device__ float  d_stats[4];

__device__ __forceinline__ uint32_t smem_u32(const void* p) {
    uint32_t a;
    asm("{ .reg .u64 t; cvta.to.shared.u64 t, %1; cvt.u32.u64 %0, t; }" : "=r"(a) : "l"(p));
    return a;
}
__device__ __forceinline__ void ldsm_x4(uint32_t* r, uint32_t addr) {
    asm volatile("ldmatrix.sync.aligned.m8n8.x4.shared.b16 {%0,%1,%2,%3}, [%4];"
                 : "=r"(r[0]), "=r"(r[1]), "=r"(r[2]), "=r"(r[3]) : "r"(addr));
}
__device__ __forceinline__ void ldsm_x4_t(uint32_t* r, uint32_t addr) {
    asm volatile("ldmatrix.sync.aligned.m8n8.x4.trans.shared.b16 {%0,%1,%2,%3}, [%4];"
                 : "=r"(r[0]), "=r"(r[1]), "=r"(r[2]), "=r"(r[3]) : "r"(addr));
}
__device__ __forceinline__ void mma_bf16(float* d, const uint32_t* a, const uint32_t* b) {
    asm volatile("mma.sync.aligned.m16n8k16.row.col.f32.bf16.bf16.f32 "
                 "{%0,%1,%2,%3}, {%4,%5,%6,%7}, {%8,%9}, {%0,%1,%2,%3};"
                 : "+f"(d[0]), "+f"(d[1]), "+f"(d[2]), "+f"(d[3])
                 : "r"(a[0]), "r"(a[1]), "r"(a[2]), "r"(a[3]), "r"(b[0]), "r"(b[1]));
}

// ---------------------------------------------------------------------------
// Prep: stacked weights (bf16 hi/lo split) + folded biases.
// rows 0..127: Wu[:, :128]@Wn ; 128..255: Wu[:,128:]@We ; 256..271: Wa1 u ;
// 272..287: Wa1 t ; 288..319: zero pad. Block GR: cA/cB.
// ---------------------------------------------------------------------------
__global__ void prep_kernel(const float* __restrict__ Wn, const float* __restrict__ We,
                            const float* __restrict__ Wa1, const float* __restrict__ Wu,
                            const float* __restrict__ bn, const float* __restrict__ be,
                            const float* __restrict__ bu) {
    __shared__ float wbuf[128];
    const int r = blockIdx.x;
    const int c = threadIdx.x;
    if (r < GR) {
        float v = 0.f;
        if (r < 128) {
            wbuf[c] = Wu[r * 256 + c];
            __syncthreads();
            #pragma unroll 8
            for (int k = 0; k < 128; k++) v += wbuf[k] * Wn[k * 128 + c];
        } else if (r < 256) {
            wbuf[c] = Wu[(r - 128) * 256 + 128 + c];
            __syncthreads();
            #pragma unroll 8
            for (int k = 0; k < 128; k++) v += wbuf[k] * We[k * 128 + c];
        } else if (r < 272) {
            v = Wa1[(r - 256) * 256 + c];
        } else if (r < 288) {
            v = Wa1[(r - 272) * 256 + 128 + c];
        }
        __nv_bfloat16 h = __float2bfloat16(v);
        d_Whi[r * 128 + c] = h;
        d_Wlo[r * 128 + c] = __float2bfloat16(v - __bfloat162float(h));
    } else {
        float a = bu[c], bb = 0.f;
        for (int k = 0; k < 128; k++) {
            a  += Wu[c * 256 + k]       * bn[k];
            bb += Wu[c * 256 + 128 + k] * be[k];
        }
        d_cA[c] = a;
        d_cB[c] = bb;
    }
}

// ---------------------------------------------------------------------------
// Tensor-core GEMM (mma.sync bf16, split hi/lo): G[b][m][p] = Wg[m]·x[b][:,p]
// One CTA: full M=320, N=64 pixels, K=128. 320 threads = 10 warps (5m x 2n),
// warp tile 64x32, m16n8k16 fragments via ldmatrix.
// SMEM: Whi 80K | Wlo 80K | Xhi 16K | Xlo 16K = 192 KB (dynamic).
// ---------------------------------------------------------------------------
#define OFF_WH 0
#define OFF_WL 81920
#define OFF_XH 163840
#define OFF_XL 180224
#define SMEM_SZ 196608

__global__ void __launch_bounds__(320, 1) mma_kernel(const float* __restrict__ x) {
    extern __shared__ __align__(16) uint8_t smem[];
    const uint32_t sb = smem_u32(smem);
    const int tid = threadIdx.x, lane = tid & 31, w = tid >> 5;
    const int wm = w >> 1, wn = w & 1;          // 5 m-warps x 2 n-warps
    const int b = blockIdx.y, p0 = blockIdx.x * 64;

    // Load W stack (hi+lo), swizzled [m][k]: row = 256B, 16 uint4/row.
    for (int i = tid; i < 5120; i += 320) {
        const int m = i >> 4, q = i & 15;
        const uint32_t off = m * 256 + ((q * 16) ^ ((m & 7) * 16));
        *(uint4*)(smem + OFF_WH + off) = ((const uint4*)d_Whi)[i];
        *(uint4*)(smem + OFF_WL + off) = ((const uint4*)d_Wlo)[i];
    }
    // Load X tile [k=128][n=64] fp32 -> bf16 hi/lo, swizzled rows of 128B.
    {
        const float* Xg = x + (size_t)b * Cd * HW + p0;
        for (int i = tid; i < 2048; i += 320) {
            const int k = i >> 4, n0 = (i & 15) * 4;
            const float4 v = *(const float4*)(Xg + (size_t)k * HW + n0);
            __nv_bfloat162 h01, h23, l01, l23;
            h01.x = __float2bfloat16(v.x); l01.x = __float2bfloat16(v.x - __bfloat162float(h01.x));
            h01.y = __float2bfloat16(v.y); l01.y = __float2bfloat16(v.y - __bfloat162float(h01.y));
            h23.x = __float2bfloat16(v.z); l23.x = __float2bfloat16(v.z - __bfloat162float(h23.x));
            h23.y = __float2bfloat16(v.w); l23.y = __float2bfloat16(v.w - __bfloat162float(h23.y));
            const uint32_t off = k * 128 + ((n0 * 2) ^ ((k & 7) * 16));
            *(__nv_bfloat162*)(smem + OFF_XH + off)     = h01;
            *(__nv_bfloat162*)(smem + OFF_XH + off + 4) = h23;
            *(__nv_bfloat162*)(smem + OFF_XL + off)     = l01;
            *(__nv_bfloat162*)(smem + OFF_XL + off + 4) = l23;
        }
    }
    __syncthreads();

    float acc[4][4][4] = {};   // [mi 16-rows][ni 8-cols][frag]

    // ldmatrix lane pattern (same for A and B-trans):
    const int lr = (lane & 7) + ((lane >> 3) & 1) * 8;   // row within 16
    const int lc = (lane >> 4) * 8;                      // col half (+8)

    #pragma unroll 1
    for (int kk = 0; kk < 8; kk++) {
        const int k0 = kk * 16;
        uint32_t ah[4][4], al[4][4];
        #pragma unroll
        for (int mi = 0; mi < 4; mi++) {
            const int row = wm * 64 + mi * 16 + lr;
            const int col = k0 + lc;
            const uint32_t off = row * 256 + ((col * 2) ^ ((row & 7) * 16));
            ldsm_x4(ah[mi], sb + OFF_WH + off);
            ldsm_x4(al[mi], sb + OFF_WL + off);
        }
        uint32_t bh[2][4], bl[2][4];
        #pragma unroll
        for (int hf = 0; hf < 2; hf++) {
            const int kr = k0 + lr;
            const int nc = wn * 32 + hf * 16 + lc;
            const uint32_t off = kr * 128 + ((nc * 2) ^ ((kr & 7) * 16));
            ldsm_x4_t(bh[hf], sb + OFF_XH + off);
            ldsm_x4_t(bl[hf], sb + OFF_XL + off);
        }
        #pragma unroll
        for (int mi = 0; mi < 4; mi++)
            #pragma unroll
            for (int ni = 0; ni < 4; ni++) {
                const uint32_t* bfh = &bh[ni >> 1][(ni & 1) * 2];
                const uint32_t* bfl = &bl[ni >> 1][(ni & 1) * 2];
                mma_bf16(acc[mi][ni], ah[mi], bfh);   // hi·hi
                mma_bf16(acc[mi][ni], al[mi], bfh);   // lo·hi
                mma_bf16(acc[mi][ni], ah[mi], bfl);   // hi·lo
            }
    }

    // Store G (rows < 288 only). d-frag: lane group = row, (lane&3)*2 = col pair.
    float* Gout = d_G + (size_t)b * GR * HW;
    const int cbase = p0 + wn * 32 + (lane & 3) * 2;
    #pragma unroll
    for (int mi = 0; mi < 4; mi++) {
        const int mb = wm * 64 + mi * 16;
        if (mb >= GUSE) break;
        const int r0 = mb + (lane >> 2);
        float* g0 = Gout + (size_t)r0 * HW + cbase;
        float* g1 = g0 + (size_t)8 * HW;
        #pragma unroll
        for (int ni = 0; ni < 4; ni++) {
            *(float2*)(g0 + ni * 8) = make_float2(acc[mi][ni][0], acc[mi][ni][1]);
            *(float2*)(g1 + ni * 8) = make_float2(acc[mi][ni][2], acc[mi][ni][3]);
        }
    }
}

// ---------------------------------------------------------------------------
// Combine: attention gates + gated neighbor aggregation + partial GN sums.
// ---------------------------------------------------------------------------
__global__ void __launch_bounds__(256) combine_kernel(const float* __restrict__ ba1,
                                                      const float* __restrict__ Wa2,
                                                      const float* __restrict__ ba2) {
    const int blk = blockIdx.x;
    const int b   = blk >> 11;
    const int p0  = (blk & 2047) << 5;
    const float* __restrict__ G = d_G + (size_t)b * GR * HW;
    float* __restrict__ nn = d_nn + (size_t)b * Cd * HW;

    __shared__ float a_s[4][32];
    __shared__ float cA_s[128], cB_s[128];
    __shared__ float red[256];

    const int tid = threadIdx.x;
    if (tid < 128) { cA_s[tid] = d_cA[tid]; cB_s[tid] = d_cB[tid]; }

    const int hrow = p0 >> 8;

    if (tid < 128) {
        const int dir = tid >> 5, px = tid & 31;
        const int p = p0 + px, wcol = p & 255;
        int off; bool valid;
        switch (dir) {
            case 0:  off = -256; valid = (hrow > 0);    break;
            case 1:  off =  256; valid = (hrow < 255);  break;
            case 2:  off =   -1; valid = (wcol > 0);    break;
            default: off =    1; valid = (wcol < 255);  break;
        }
        float a = 0.f;
        if (valid) {
            float logit = ba2[0];
            const float* Gu = G + 256 * HW + p;
            const float* Gt = G + 272 * HW + p + off;
            #pragma unroll
            for (int i = 0; i < 16; i++) {
                float hv = Gu[i * HW] + Gt[i * HW] + ba1[i];
                hv = hv > 0.f ? hv : 0.2f * hv;
                logit += Wa2[i] * hv;
            }
            a = 1.f / (1.f + expf(-logit));
        }
        a_s[dir][px] = a;
    }
    __syncthreads();

    const int wq = tid >> 5, lane = tid & 31;
    const int p = p0 + lane;
    const float au = a_s[0][lane], ad = a_s[1][lane];
    const float al = a_s[2][lane], ar = a_s[3][lane];

    float lsum = 0.f, lsq = 0.f;
    #pragma unroll
    for (int ci = 0; ci < 16; ci++) {
        const int c = (wq << 4) + ci;
        const float* z = G + (size_t)c * HW;
        const float* y = G + (size_t)(128 + c) * HW;
        const float cb = cB_s[c];
        float v = z[p] + cA_s[c]
                + au * (y[p - 256] + cb) + ad * (y[p + 256] + cb)
                + al * (y[p - 1]   + cb) + ar * (y[p + 1]   + cb);
        nn[(size_t)c * HW + p] = v;
        lsum += v; lsq += v * v;
    }

    red[tid] = lsum; __syncthreads();
    for (int s = 128; s > 0; s >>= 1) { if (tid < s) red[tid] += red[tid + s]; __syncthreads(); }
    if (tid == 0) d_part[blk * 2] = (double)red[0];
    __syncthreads();
    red[tid] = lsq; __syncthreads();
    for (int s = 128; s > 0; s >>= 1) { if (tid < s) red[tid] += red[tid + s]; __syncthreads(); }
    if (tid == 0) d_part[blk * 2 + 1] = (double)red[0];
}

// ---------------------------------------------------------------------------
// Finalize GroupNorm stats (deterministic).
// ---------------------------------------------------------------------------
__global__ void __launch_bounds__(512) finalize_kernel() {
    const int b = blockIdx.x;
    __shared__ double rs[512], rq[512];
    double s = 0.0, q = 0.0;
    for (int i = threadIdx.x; i < 2048; i += 512) {
        s += d_part[(b * 2048 + i) * 2];
        q += d_part[(b * 2048 + i) * 2 + 1];
    }
    rs[threadIdx.x] = s; rq[threadIdx.x] = q; __syncthreads();
    for (int st = 256; st > 0; st >>= 1) {
        if (threadIdx.x < st) { rs[threadIdx.x] += rs[threadIdx.x + st]; rq[threadIdx.x] += rq[threadIdx.x + st]; }
        __syncthreads();
    }
    if (threadIdx.x == 0) {
        const double N = (double)Cd * HW;
        const double mu = rs[0] / N;
        const double var = rq[0] / N - mu * mu;
        d_stats[b * 2]     = (float)mu;
        d_stats[b * 2 + 1] = (float)rsqrt(var + EPSV);
    }
}

// ---------------------------------------------------------------------------
// Epilogue: out = relu((nn - mu)*rsig*gamma + beta) + x
// ---------------------------------------------------------------------------
__global__ void __launch_bounds__(256) final_kernel(const float* __restrict__ x,
                                                    const float* __restrict__ gamma,
                                                    const float* __restrict__ beta,
                                                    float* __restrict__ out) {
    const int idx4 = blockIdx.x * blockDim.x + threadIdx.x;
    const int b = idx4 >> 21;
    const int c = (idx4 >> 14) & 127;
    const float mu = d_stats[b * 2], rs = d_stats[b * 2 + 1];
    const float g  = gamma[c] * rs;
    const float bt = beta[c] - mu * g;
    const float4 v  = ((const float4*)d_nn)[idx4];
    const float4 xv = ((const float4*)x)[idx4];
    float4 o;
    o.x = fmaxf(v.x * g + bt, 0.f) + xv.x;
    o.y = fmaxf(v.y * g + bt, 0.f) + xv.y;
    o.z = fmaxf(v.z * g + bt, 0.f) + xv.z;
    o.w = fmaxf(v.w * g + bt, 0.f) + xv.w;
    ((float4*)out)[idx4] = o;
}

// ---------------------------------------------------------------------------
// Launch
// ---------------------------------------------------------------------------
extern "C" void kernel_launch(void* const* d_in, const int* in_sizes, int n_in,
                              void* d_out, int out_size) {
    const float* x     = (const float*)d_in[0];
    const float* Wn    = (const float*)d_in[1];
    const float* bn    = (const float*)d_in[2];
    const float* We    = (const float*)d_in[3];
    const float* be    = (const float*)d_in[4];
    const float* Wa1   = (const float*)d_in[5];
    const float* ba1   = (const float*)d_in[6];
    const float* Wa2   = (const float*)d_in[7];
    const float* ba2   = (const float*)d_in[8];
    const float* Wu    = (const float*)d_in[9];
    const float* bu    = (const float*)d_in[10];
    const float* gamma = (const float*)d_in[11];
    const float* beta  = (const float*)d_in[12];
    float* out = (float*)d_out;

    cudaFuncSetAttribute(mma_kernel, cudaFuncAttributeMaxDynamicSharedMemorySize, SMEM_SZ);

    prep_kernel<<<GR + 1, 128>>>(Wn, We, Wa1, Wu, bn, be, bu);
    mma_kernel<<<dim3(HW / 64, Bd), 320, SMEM_SZ>>>(x);
    combine_kernel<<<4096, 256>>>(ba1, Wa2, ba2);
    finalize_kernel<<<2, 512>>>();
    final_kernel<<<(Bd * Cd * HW / 4) / 256, 256>>>(x, gamma, beta, out);
}

// round 6
// speedup vs baseline: 1.8460x; 1.4051x over previous
#include <cuda_runtime.h>
#include <cuda_bf16.h>
#include <math.h>
#include <stdint.h>

// Problem constants
#define Bd   2
#define Cd   128
#define HW   65536          // 256*256
#define GR   320            // stacked M (z 0..127, y 128..255, u 256..271, t 272..287, pad..319)
#define GUSE 288            // rows actually stored/used
#define EPSV 1e-5
#define NTILE 2048          // 64-pixel tiles total (1024 per batch * 2 batches)
#define NCTA  152           // persistent CTAs (1 per GB300 SM)

// ---------------------------------------------------------------------------
// Scratch (device globals: allocation-free kernel_launch)
// ---------------------------------------------------------------------------
__device__ __nv_bfloat16 d_Whi[GR * 128];
__device__ __nv_bfloat16 d_Wlo[GR * 128];
__device__ float  d_cA[128];
__device__ float  d_cB[128];
__device__ float  d_G[(size_t)Bd * GR * HW];
__device__ float  d_nn[(size_t)Bd * Cd * HW];
__device__ double d_part[4096 * 2];
__device__ float  d_stats[4];
__device__ unsigned d_count = 0;

__device__ __forceinline__ uint32_t smem_u32(const void* p) {
    uint32_t a;
    asm("{ .reg .u64 t; cvta.to.shared.u64 t, %1; cvt.u32.u64 %0, t; }" : "=r"(a) : "l"(p));
    return a;
}
__device__ __forceinline__ void ldsm_x4(uint32_t* r, uint32_t addr) {
    asm volatile("ldmatrix.sync.aligned.m8n8.x4.shared.b16 {%0,%1,%2,%3}, [%4];"
                 : "=r"(r[0]), "=r"(r[1]), "=r"(r[2]), "=r"(r[3]) : "r"(addr));
}
__device__ __forceinline__ void ldsm_x4_t(uint32_t* r, uint32_t addr) {
    asm volatile("ldmatrix.sync.aligned.m8n8.x4.trans.shared.b16 {%0,%1,%2,%3}, [%4];"
                 : "=r"(r[0]), "=r"(r[1]), "=r"(r[2]), "=r"(r[3]) : "r"(addr));
}
__device__ __forceinline__ void mma_bf16(float* d, const uint32_t* a, const uint32_t* b) {
    asm volatile("mma.sync.aligned.m16n8k16.row.col.f32.bf16.bf16.f32 "
                 "{%0,%1,%2,%3}, {%4,%5,%6,%7}, {%8,%9}, {%0,%1,%2,%3};"
                 : "+f"(d[0]), "+f"(d[1]), "+f"(d[2]), "+f"(d[3])
                 : "r"(a[0]), "r"(a[1]), "r"(a[2]), "r"(a[3]), "r"(b[0]), "r"(b[1]));
}

// ---------------------------------------------------------------------------
// Prep: stacked weights (bf16 hi/lo split) + folded biases.
// ---------------------------------------------------------------------------
__global__ void prep_kernel(const float* __restrict__ Wn, const float* __restrict__ We,
                            const float* __restrict__ Wa1, const float* __restrict__ Wu,
                            const float* __restrict__ bn, const float* __restrict__ be,
                            const float* __restrict__ bu) {
    __shared__ float wbuf[128];
    const int r = blockIdx.x;
    const int c = threadIdx.x;
    if (r < GR) {
        float v = 0.f;
        if (r < 128) {
            wbuf[c] = Wu[r * 256 + c];
            __syncthreads();
            #pragma unroll 8
            for (int k = 0; k < 128; k++) v += wbuf[k] * Wn[k * 128 + c];
        } else if (r < 256) {
            wbuf[c] = Wu[(r - 128) * 256 + 128 + c];
            __syncthreads();
            #pragma unroll 8
            for (int k = 0; k < 128; k++) v += wbuf[k] * We[k * 128 + c];
        } else if (r < 272) {
            v = Wa1[(r - 256) * 256 + c];
        } else if (r < 288) {
            v = Wa1[(r - 272) * 256 + 128 + c];
        }
        __nv_bfloat16 h = __float2bfloat16(v);
        d_Whi[r * 128 + c] = h;
        d_Wlo[r * 128 + c] = __float2bfloat16(v - __bfloat162float(h));
    } else {
        float a = bu[c], bb = 0.f;
        for (int k = 0; k < 128; k++) {
            a  += Wu[c * 256 + k]       * bn[k];
            bb += Wu[c * 256 + 128 + k] * be[k];
        }
        d_cA[c] = a;
        d_cB[c] = bb;
    }
}

// ---------------------------------------------------------------------------
// Persistent tensor-core GEMM (mma.sync bf16 split hi/lo).
// Grid = 152 CTAs, each loops over 64-pixel tiles (1024/batch). Weights
// resident in SMEM; X tiles register-prefetched + double-buffered.
// SMEM: Whi 80K | Wlo 80K | X stage0 (hi16K+lo16K) | X stage1 = 224 KB.
// ---------------------------------------------------------------------------
#define OFF_WH  0
#define OFF_WL  81920
#define OFF_X   163840
#define XSTAGE  32768
#define SMEM_SZ 229376

__global__ void __launch_bounds__(320, 1) mma_kernel(const float* __restrict__ x) {
    extern __shared__ __align__(16) uint8_t smem[];
    const uint32_t sb = smem_u32(smem);
    const int tid = threadIdx.x, lane = tid & 31, w = tid >> 5;
    const int wm = w >> 1, wn = w & 1;          // 5 m-warps x 2 n-warps
    const int miN = (wm == 4) ? 2 : 4;          // skip pad rows 288..319

    // Load W stack once (hi+lo), swizzled [m][k]: row = 256B, 16 uint4/row.
    for (int i = tid; i < 5120; i += 320) {
        const int m = i >> 4, q = i & 15;
        const uint32_t off = m * 256 + ((q * 16) ^ ((m & 7) * 16));
        *(uint4*)(smem + OFF_WH + off) = ((const uint4*)d_Whi)[i];
        *(uint4*)(smem + OFF_WL + off) = ((const uint4*)d_Wlo)[i];
    }

    // ldmatrix lane pattern (same for A and B-trans):
    const int lr = (lane & 7) + ((lane >> 3) & 1) * 8;
    const int lc = (lane >> 4) * 8;

    // Register prefetch of first tile's X block (7 float4 per thread max).
    float4 xpre[7];
    const int t0 = blockIdx.x;
    {
        const int b = t0 >> 10, p0 = (t0 & 1023) << 6;
        const float* Xg = x + (size_t)b * Cd * HW + p0;
        #pragma unroll
        for (int j = 0; j < 7; j++) {
            const int i = tid + j * 320;
            if (i < 2048) xpre[j] = *(const float4*)(Xg + (size_t)(i >> 4) * HW + (i & 15) * 4);
        }
    }

    int stage = 0;
    for (int t = t0; t < NTILE; t += NCTA) {
        const int b = t >> 10, p0 = (t & 1023) << 6;
        const uint32_t xh = OFF_X + stage * XSTAGE;
        const uint32_t xl = xh + 16384;

        // Convert prefetched fp32 -> bf16 hi/lo into this stage.
        #pragma unroll
        for (int j = 0; j < 7; j++) {
            const int i = tid + j * 320;
            if (i < 2048) {
                const float4 v = xpre[j];
                const int k = i >> 4, n0 = (i & 15) * 4;
                __nv_bfloat162 h01, h23, l01, l23;
                h01.x = __float2bfloat16(v.x); l01.x = __float2bfloat16(v.x - __bfloat162float(h01.x));
                h01.y = __float2bfloat16(v.y); l01.y = __float2bfloat16(v.y - __bfloat162float(h01.y));
                h23.x = __float2bfloat16(v.z); l23.x = __float2bfloat16(v.z - __bfloat162float(h23.x));
                h23.y = __float2bfloat16(v.w); l23.y = __float2bfloat16(v.w - __bfloat162float(h23.y));
                const uint32_t off = k * 128 + ((n0 * 2) ^ ((k & 7) * 16));
                uint2 hp, lp;
                hp.x = *(uint32_t*)&h01; hp.y = *(uint32_t*)&h23;
                lp.x = *(uint32_t*)&l01; lp.y = *(uint32_t*)&l23;
                *(uint2*)(smem + xh + off) = hp;
                *(uint2*)(smem + xl + off) = lp;
            }
        }
        __syncthreads();

        // Prefetch next tile's X (overlaps with compute below).
        const int tn = t + NCTA;
        if (tn < NTILE) {
            const int bn_ = tn >> 10, pn = (tn & 1023) << 6;
            const float* Xg = x + (size_t)bn_ * Cd * HW + pn;
            #pragma unroll
            for (int j = 0; j < 7; j++) {
                const int i = tid + j * 320;
                if (i < 2048) xpre[j] = *(const float4*)(Xg + (size_t)(i >> 4) * HW + (i & 15) * 4);
            }
        }

        // Compute: K loop over 8 chunks of 16.
        float acc[4][4][4] = {};
        #pragma unroll 1
        for (int kk = 0; kk < 8; kk++) {
            const int k0 = kk * 16;
            uint32_t ah[4][4], al[4][4];
            #pragma unroll
            for (int mi = 0; mi < 4; mi++) {
                if (mi >= miN) break;
                const int row = wm * 64 + mi * 16 + lr;
                const int col = k0 + lc;
                const uint32_t off = row * 256 + ((col * 2) ^ ((row & 7) * 16));
                ldsm_x4(ah[mi], sb + OFF_WH + off);
                ldsm_x4(al[mi], sb + OFF_WL + off);
            }
            uint32_t bh[2][4], bl[2][4];
            #pragma unroll
            for (int hf = 0; hf < 2; hf++) {
                const int kr = k0 + lr;
                const int nc = wn * 32 + hf * 16 + lc;
                const uint32_t off = kr * 128 + ((nc * 2) ^ ((kr & 7) * 16));
                ldsm_x4_t(bh[hf], sb + xh + off);
                ldsm_x4_t(bl[hf], sb + xl + off);
            }
            #pragma unroll
            for (int mi = 0; mi < 4; mi++) {
                if (mi >= miN) break;
                #pragma unroll
                for (int ni = 0; ni < 4; ni++) {
                    const uint32_t* bfh = &bh[ni >> 1][(ni & 1) * 2];
                    const uint32_t* bfl = &bl[ni >> 1][(ni & 1) * 2];
                    mma_bf16(acc[mi][ni], ah[mi], bfh);   // hi·hi
                    mma_bf16(acc[mi][ni], al[mi], bfh);   // lo·hi
                    mma_bf16(acc[mi][ni], ah[mi], bfl);   // hi·lo
                }
            }
        }

        // Store G rows < 288.
        float* Gout = d_G + (size_t)b * GR * HW;
        const int cbase = p0 + wn * 32 + (lane & 3) * 2;
        #pragma unroll
        for (int mi = 0; mi < 4; mi++) {
            const int mb = wm * 64 + mi * 16;
            if (mb >= GUSE) break;
            const int r0 = mb + (lane >> 2);
            float* g0 = Gout + (size_t)r0 * HW + cbase;
            float* g1 = g0 + (size_t)8 * HW;
            #pragma unroll
            for (int ni = 0; ni < 4; ni++) {
                *(float2*)(g0 + ni * 8) = make_float2(acc[mi][ni][0], acc[mi][ni][1]);
                *(float2*)(g1 + ni * 8) = make_float2(acc[mi][ni][2], acc[mi][ni][3]);
            }
        }
        stage ^= 1;
    }
}

// ---------------------------------------------------------------------------
// Combine: attention gates + gated aggregation + partial GN sums.
// Last block (threadfence-reduction) computes per-batch stats. Deterministic.
// ---------------------------------------------------------------------------
__global__ void __launch_bounds__(256) combine_kernel(const float* __restrict__ ba1,
                                                      const float* __restrict__ Wa2,
                                                      const float* __restrict__ ba2) {
    const int blk = blockIdx.x;
    const int b   = blk >> 11;
    const int p0  = (blk & 2047) << 5;
    const float* __restrict__ G = d_G + (size_t)b * GR * HW;
    float* __restrict__ nn = d_nn + (size_t)b * Cd * HW;

    __shared__ float a_s[4][32];
    __shared__ float cA_s[128], cB_s[128];
    __shared__ float red[256];

    const int tid = threadIdx.x;
    if (tid < 128) { cA_s[tid] = d_cA[tid]; cB_s[tid] = d_cB[tid]; }

    const int hrow = p0 >> 8;

    if (tid < 128) {
        const int dir = tid >> 5, px = tid & 31;
        const int p = p0 + px, wcol = p & 255;
        int off; bool valid;
        switch (dir) {
            case 0:  off = -256; valid = (hrow > 0);    break;
            case 1:  off =  256; valid = (hrow < 255);  break;
            case 2:  off =   -1; valid = (wcol > 0);    break;
            default: off =    1; valid = (wcol < 255);  break;
        }
        float a = 0.f;
        if (valid) {
            float logit = ba2[0];
            const float* Gu = G + 256 * HW + p;
            const float* Gt = G + 272 * HW + p + off;
            #pragma unroll
            for (int i = 0; i < 16; i++) {
                float hv = Gu[i * HW] + Gt[i * HW] + ba1[i];
                hv = hv > 0.f ? hv : 0.2f * hv;
                logit += Wa2[i] * hv;
            }
            a = 1.f / (1.f + expf(-logit));
        }
        a_s[dir][px] = a;
    }
    __syncthreads();

    const int wq = tid >> 5, lane = tid & 31;
    const int p = p0 + lane;
    const float au = a_s[0][lane], ad = a_s[1][lane];
    const float al = a_s[2][lane], ar = a_s[3][lane];

    float lsum = 0.f, lsq = 0.f;
    #pragma unroll
    for (int ci = 0; ci < 16; ci++) {
        const int c = (wq << 4) + ci;
        const float* z = G + (size_t)c * HW;
        const float* y = G + (size_t)(128 + c) * HW;
        const float cb = cB_s[c];
        float v = z[p] + cA_s[c]
                + au * (y[p - 256] + cb) + ad * (y[p + 256] + cb)
                + al * (y[p - 1]   + cb) + ar * (y[p + 1]   + cb);
        nn[(size_t)c * HW + p] = v;
        lsum += v; lsq += v * v;
    }

    red[tid] = lsum; __syncthreads();
    for (int s = 128; s > 0; s >>= 1) { if (tid < s) red[tid] += red[tid + s]; __syncthreads(); }
    if (tid == 0) d_part[blk * 2] = (double)red[0];
    __syncthreads();
    red[tid] = lsq; __syncthreads();
    for (int s = 128; s > 0; s >>= 1) { if (tid < s) red[tid] += red[tid + s]; __syncthreads(); }
    if (tid == 0) d_part[blk * 2 + 1] = (double)red[0];

    // Last-block GroupNorm finalize (threadfence-reduction pattern).
    __shared__ unsigned isLast;
    __threadfence();
    if (tid == 0) isLast = (atomicAdd(&d_count, 1u) == 4095u) ? 1u : 0u;
    __syncthreads();
    if (isLast) {
        __threadfence();
        __shared__ double rs[256], rq[256];
        for (int bb = 0; bb < Bd; bb++) {
            double s = 0.0, q = 0.0;
            for (int i = tid; i < 2048; i += 256) {
                s += d_part[(bb * 2048 + i) * 2];
                q += d_part[(bb * 2048 + i) * 2 + 1];
            }
            rs[tid] = s; rq[tid] = q; __syncthreads();
            for (int st = 128; st > 0; st >>= 1) {
                if (tid < st) { rs[tid] += rs[tid + st]; rq[tid] += rq[tid + st]; }
                __syncthreads();
            }
            if (tid == 0) {
                const double N = (double)Cd * HW;
                const double mu = rs[0] / N;
                const double var = rq[0] / N - mu * mu;
                d_stats[bb * 2]     = (float)mu;
                d_stats[bb * 2 + 1] = (float)rsqrt(var + EPSV);
            }
            __syncthreads();
        }
        if (tid == 0) d_count = 0;   // self-reset for next graph replay
    }
}

// ---------------------------------------------------------------------------
// Epilogue: out = relu((nn - mu)*rsig*gamma + beta) + x
// ---------------------------------------------------------------------------
__global__ void __launch_bounds__(256) final_kernel(const float* __restrict__ x,
                                                    const float* __restrict__ gamma,
                                                    const float* __restrict__ beta,
                                                    float* __restrict__ out) {
    const int idx4 = blockIdx.x * blockDim.x + threadIdx.x;
    const int b = idx4 >> 21;
    const int c = (idx4 >> 14) & 127;
    const float mu = d_stats[b * 2], rs = d_stats[b * 2 + 1];
    const float g  = gamma[c] * rs;
    const float bt = beta[c] - mu * g;
    const float4 v  = ((const float4*)d_nn)[idx4];
    const float4 xv = ((const float4*)x)[idx4];
    float4 o;
    o.x = fmaxf(v.x * g + bt, 0.f) + xv.x;
    o.y = fmaxf(v.y * g + bt, 0.f) + xv.y;
    o.z = fmaxf(v.z * g + bt, 0.f) + xv.z;
    o.w = fmaxf(v.w * g + bt, 0.f) + xv.w;
    ((float4*)out)[idx4] = o;
}

// ---------------------------------------------------------------------------
// Launch
// ---------------------------------------------------------------------------
extern "C" void kernel_launch(void* const* d_in, const int* in_sizes, int n_in,
                              void* d_out, int out_size) {
    const float* x     = (const float*)d_in[0];
    const float* Wn    = (const float*)d_in[1];
    const float* bn    = (const float*)d_in[2];
    const float* We    = (const float*)d_in[3];
    const float* be    = (const float*)d_in[4];
    const float* Wa1   = (const float*)d_in[5];
    const float* ba1   = (const float*)d_in[6];
    const float* Wa2   = (const float*)d_in[7];
    const float* ba2   = (const float*)d_in[8];
    const float* Wu    = (const float*)d_in[9];
    const float* bu    = (const float*)d_in[10];
    const float* gamma = (const float*)d_in[11];
    const float* beta  = (const float*)d_in[12];
    float* out = (float*)d_out;

    cudaFuncSetAttribute(mma_kernel, cudaFuncAttributeMaxDynamicSharedMemorySize, SMEM_SZ);

    prep_kernel<<<GR + 1, 128>>>(Wn, We, Wa1, Wu, bn, be, bu);
    mma_kernel<<<NCTA, 320, SMEM_SZ>>>(x);
    combine_kernel<<<4096, 256>>>(ba1, Wa2, ba2);
    final_kernel<<<(Bd * Cd * HW / 4) / 256, 256>>>(x, gamma, beta, out);
}

// round 7
// speedup vs baseline: 1.8703x; 1.0132x over previous
#include <cuda_runtime.h>
#include <cuda_bf16.h>
#include <cuda_fp16.h>
#include <math.h>
#include <stdint.h>

// Problem constants
#define Bd   2
#define Cd   128
#define HW   65536          // 256*256
#define GR   320            // stacked M (z 0..127, y 128..255, u 256..271, t 272..287, pad..319)
#define GUSE 288            // rows actually stored/used
#define EPSV 1e-5
#define NTILE 2048          // 64-pixel tiles total (1024 per batch * 2 batches)
#define NCTA  152           // persistent CTAs (1 per GB300 SM)

// ---------------------------------------------------------------------------
// Scratch (device globals: allocation-free kernel_launch)
// ---------------------------------------------------------------------------
__device__ __nv_bfloat16 d_Whi[GR * 128];
__device__ __nv_bfloat16 d_Wlo[GR * 128];
__device__ float  d_cA[128];
__device__ float  d_cB[128];
__device__ __half d_G[(size_t)Bd * GR * HW];    // fp16 stacked GEMM output
__device__ __half d_nn[(size_t)Bd * Cd * HW];   // fp16 pre-norm activations
__device__ double d_part[4096 * 2];
__device__ float  d_stats[4];
__device__ unsigned d_count = 0;

__device__ __forceinline__ uint32_t smem_u32(const void* p) {
    uint32_t a;
    asm("{ .reg .u64 t; cvta.to.shared.u64 t, %1; cvt.u32.u64 %0, t; }" : "=r"(a) : "l"(p));
    return a;
}
__device__ __forceinline__ void ldsm_x4(uint32_t* r, uint32_t addr) {
    asm volatile("ldmatrix.sync.aligned.m8n8.x4.shared.b16 {%0,%1,%2,%3}, [%4];"
                 : "=r"(r[0]), "=r"(r[1]), "=r"(r[2]), "=r"(r[3]) : "r"(addr));
}
__device__ __forceinline__ void ldsm_x4_t(uint32_t* r, uint32_t addr) {
    asm volatile("ldmatrix.sync.aligned.m8n8.x4.trans.shared.b16 {%0,%1,%2,%3}, [%4];"
                 : "=r"(r[0]), "=r"(r[1]), "=r"(r[2]), "=r"(r[3]) : "r"(addr));
}
__device__ __forceinline__ void mma_bf16(float* d, const uint32_t* a, const uint32_t* b) {
    asm volatile("mma.sync.aligned.m16n8k16.row.col.f32.bf16.bf16.f32 "
                 "{%0,%1,%2,%3}, {%4,%5,%6,%7}, {%8,%9}, {%0,%1,%2,%3};"
                 : "+f"(d[0]), "+f"(d[1]), "+f"(d[2]), "+f"(d[3])
                 : "r"(a[0]), "r"(a[1]), "r"(a[2]), "r"(a[3]), "r"(b[0]), "r"(b[1]));
}

// ---------------------------------------------------------------------------
// Prep: stacked weights (bf16 hi/lo split) + folded biases.
// ---------------------------------------------------------------------------
__global__ void prep_kernel(const float* __restrict__ Wn, const float* __restrict__ We,
                            const float* __restrict__ Wa1, const float* __restrict__ Wu,
                            const float* __restrict__ bn, const float* __restrict__ be,
                            const float* __restrict__ bu) {
    __shared__ float wbuf[128];
    const int r = blockIdx.x;
    const int c = threadIdx.x;
    if (r < GR) {
        float v = 0.f;
        if (r < 128) {
            wbuf[c] = Wu[r * 256 + c];
            __syncthreads();
            #pragma unroll 8
            for (int k = 0; k < 128; k++) v += wbuf[k] * Wn[k * 128 + c];
        } else if (r < 256) {
            wbuf[c] = Wu[(r - 128) * 256 + 128 + c];
            __syncthreads();
            #pragma unroll 8
            for (int k = 0; k < 128; k++) v += wbuf[k] * We[k * 128 + c];
        } else if (r < 272) {
            v = Wa1[(r - 256) * 256 + c];
        } else if (r < 288) {
            v = Wa1[(r - 272) * 256 + 128 + c];
        }
        __nv_bfloat16 h = __float2bfloat16(v);
        d_Whi[r * 128 + c] = h;
        d_Wlo[r * 128 + c] = __float2bfloat16(v - __bfloat162float(h));
    } else {
        float a = bu[c], bb = 0.f;
        for (int k = 0; k < 128; k++) {
            a  += Wu[c * 256 + k]       * bn[k];
            bb += Wu[c * 256 + 128 + k] * be[k];
        }
        d_cA[c] = a;
        d_cB[c] = bb;
    }
}

// ---------------------------------------------------------------------------
// Persistent tensor-core GEMM (mma.sync bf16 split hi/lo). G stored fp16.
// ---------------------------------------------------------------------------
#define OFF_WH  0
#define OFF_WL  81920
#define OFF_X   163840
#define XSTAGE  32768
#define SMEM_SZ 229376

__global__ void __launch_bounds__(320, 1) mma_kernel(const float* __restrict__ x) {
    extern __shared__ __align__(16) uint8_t smem[];
    const uint32_t sb = smem_u32(smem);
    const int tid = threadIdx.x, lane = tid & 31, w = tid >> 5;
    const int wm = w >> 1, wn = w & 1;          // 5 m-warps x 2 n-warps
    const int miN = (wm == 4) ? 2 : 4;          // skip pad rows 288..319

    // Load W stack once (hi+lo), swizzled [m][k]: row = 256B, 16 uint4/row.
    for (int i = tid; i < 5120; i += 320) {
        const int m = i >> 4, q = i & 15;
        const uint32_t off = m * 256 + ((q * 16) ^ ((m & 7) * 16));
        *(uint4*)(smem + OFF_WH + off) = ((const uint4*)d_Whi)[i];
        *(uint4*)(smem + OFF_WL + off) = ((const uint4*)d_Wlo)[i];
    }

    const int lr = (lane & 7) + ((lane >> 3) & 1) * 8;
    const int lc = (lane >> 4) * 8;

    // Register prefetch of first tile's X block (7 float4 per thread max).
    float4 xpre[7];
    const int t0 = blockIdx.x;
    {
        const int b = t0 >> 10, p0 = (t0 & 1023) << 6;
        const float* Xg = x + (size_t)b * Cd * HW + p0;
        #pragma unroll
        for (int j = 0; j < 7; j++) {
            const int i = tid + j * 320;
            if (i < 2048) xpre[j] = *(const float4*)(Xg + (size_t)(i >> 4) * HW + (i & 15) * 4);
        }
    }

    int stage = 0;
    for (int t = t0; t < NTILE; t += NCTA) {
        const int b = t >> 10, p0 = (t & 1023) << 6;
        const uint32_t xh = OFF_X + stage * XSTAGE;
        const uint32_t xl = xh + 16384;

        // Convert prefetched fp32 -> bf16 hi/lo into this stage.
        #pragma unroll
        for (int j = 0; j < 7; j++) {
            const int i = tid + j * 320;
            if (i < 2048) {
                const float4 v = xpre[j];
                const int k = i >> 4, n0 = (i & 15) * 4;
                __nv_bfloat162 h01, h23, l01, l23;
                h01.x = __float2bfloat16(v.x); l01.x = __float2bfloat16(v.x - __bfloat162float(h01.x));
                h01.y = __float2bfloat16(v.y); l01.y = __float2bfloat16(v.y - __bfloat162float(h01.y));
                h23.x = __float2bfloat16(v.z); l23.x = __float2bfloat16(v.z - __bfloat162float(h23.x));
                h23.y = __float2bfloat16(v.w); l23.y = __float2bfloat16(v.w - __bfloat162float(h23.y));
                const uint32_t off = k * 128 + ((n0 * 2) ^ ((k & 7) * 16));
                uint2 hp, lp;
                hp.x = *(uint32_t*)&h01; hp.y = *(uint32_t*)&h23;
                lp.x = *(uint32_t*)&l01; lp.y = *(uint32_t*)&l23;
                *(uint2*)(smem + xh + off) = hp;
                *(uint2*)(smem + xl + off) = lp;
            }
        }
        __syncthreads();

        // Prefetch next tile's X (overlaps with compute below).
        const int tn = t + NCTA;
        if (tn < NTILE) {
            const int bn_ = tn >> 10, pn = (tn & 1023) << 6;
            const float* Xg = x + (size_t)bn_ * Cd * HW + pn;
            #pragma unroll
            for (int j = 0; j < 7; j++) {
                const int i = tid + j * 320;
                if (i < 2048) xpre[j] = *(const float4*)(Xg + (size_t)(i >> 4) * HW + (i & 15) * 4);
            }
        }

        // Compute: K loop over 8 chunks of 16.
        float acc[4][4][4] = {};
        #pragma unroll 1
        for (int kk = 0; kk < 8; kk++) {
            const int k0 = kk * 16;
            uint32_t ah[4][4], al[4][4];
            #pragma unroll
            for (int mi = 0; mi < 4; mi++) {
                if (mi >= miN) break;
                const int row = wm * 64 + mi * 16 + lr;
                const int col = k0 + lc;
                const uint32_t off = row * 256 + ((col * 2) ^ ((row & 7) * 16));
                ldsm_x4(ah[mi], sb + OFF_WH + off);
                ldsm_x4(al[mi], sb + OFF_WL + off);
            }
            uint32_t bh[2][4], bl[2][4];
            #pragma unroll
            for (int hf = 0; hf < 2; hf++) {
                const int kr = k0 + lr;
                const int nc = wn * 32 + hf * 16 + lc;
                const uint32_t off = kr * 128 + ((nc * 2) ^ ((kr & 7) * 16));
                ldsm_x4_t(bh[hf], sb + xh + off);
                ldsm_x4_t(bl[hf], sb + xl + off);
            }
            #pragma unroll
            for (int mi = 0; mi < 4; mi++) {
                if (mi >= miN) break;
                #pragma unroll
                for (int ni = 0; ni < 4; ni++) {
                    const uint32_t* bfh = &bh[ni >> 1][(ni & 1) * 2];
                    const uint32_t* bfl = &bl[ni >> 1][(ni & 1) * 2];
                    mma_bf16(acc[mi][ni], ah[mi], bfh);   // hi·hi
                    mma_bf16(acc[mi][ni], al[mi], bfh);   // lo·hi
                    mma_bf16(acc[mi][ni], ah[mi], bfl);   // hi·lo
                }
            }
        }

        // Store G rows < 288 as fp16 (half2 pairs).
        __half* Gout = d_G + (size_t)b * GR * HW;
        const int cbase = p0 + wn * 32 + (lane & 3) * 2;
        #pragma unroll
        for (int mi = 0; mi < 4; mi++) {
            const int mb = wm * 64 + mi * 16;
            if (mb >= GUSE) break;
            const int r0 = mb + (lane >> 2);
            __half* g0 = Gout + (size_t)r0 * HW + cbase;
            __half* g1 = g0 + (size_t)8 * HW;
            #pragma unroll
            for (int ni = 0; ni < 4; ni++) {
                *(__half2*)(g0 + ni * 8) = __floats2half2_rn(acc[mi][ni][0], acc[mi][ni][1]);
                *(__half2*)(g1 + ni * 8) = __floats2half2_rn(acc[mi][ni][2], acc[mi][ni][3]);
            }
        }
        stage ^= 1;
    }
}

// ---------------------------------------------------------------------------
// Combine: attention gates + gated aggregation + partial GN sums (fp16 G/nn).
// Stats accumulated from the fp16-rounded values (consistent with storage).
// Last block computes per-batch stats (threadfence-reduction). Deterministic.
// ---------------------------------------------------------------------------
__global__ void __launch_bounds__(256) combine_kernel(const float* __restrict__ ba1,
                                                      const float* __restrict__ Wa2,
                                                      const float* __restrict__ ba2) {
    const int blk = blockIdx.x;
    const int b   = blk >> 11;
    const int p0  = (blk & 2047) << 5;
    const __half* __restrict__ G = d_G + (size_t)b * GR * HW;
    __half* __restrict__ nn = d_nn + (size_t)b * Cd * HW;

    __shared__ float a_s[4][32];
    __shared__ float cA_s[128], cB_s[128];
    __shared__ float red[256];

    const int tid = threadIdx.x;
    if (tid < 128) { cA_s[tid] = d_cA[tid]; cB_s[tid] = d_cB[tid]; }

    const int hrow = p0 >> 8;

    if (tid < 128) {
        const int dir = tid >> 5, px = tid & 31;
        const int p = p0 + px, wcol = p & 255;
        int off; bool valid;
        switch (dir) {
            case 0:  off = -256; valid = (hrow > 0);    break;
            case 1:  off =  256; valid = (hrow < 255);  break;
            case 2:  off =   -1; valid = (wcol > 0);    break;
            default: off =    1; valid = (wcol < 255);  break;
        }
        float a = 0.f;
        if (valid) {
            float logit = ba2[0];
            const __half* Gu = G + 256 * HW + p;
            const __half* Gt = G + 272 * HW + p + off;
            #pragma unroll
            for (int i = 0; i < 16; i++) {
                float hv = __half2float(Gu[i * HW]) + __half2float(Gt[i * HW]) + ba1[i];
                hv = hv > 0.f ? hv : 0.2f * hv;
                logit += Wa2[i] * hv;
            }
            a = 1.f / (1.f + expf(-logit));
        }
        a_s[dir][px] = a;
    }
    __syncthreads();

    const int wq = tid >> 5, lane = tid & 31;
    const int p = p0 + lane;
    const float au = a_s[0][lane], ad = a_s[1][lane];
    const float al = a_s[2][lane], ar = a_s[3][lane];

    float lsum = 0.f, lsq = 0.f;
    #pragma unroll
    for (int ci = 0; ci < 16; ci++) {
        const int c = (wq << 4) + ci;
        const __half* z = G + (size_t)c * HW;
        const __half* y = G + (size_t)(128 + c) * HW;
        const float cb = cB_s[c];
        float v = __half2float(z[p]) + cA_s[c]
                + au * (__half2float(y[p - 256]) + cb) + ad * (__half2float(y[p + 256]) + cb)
                + al * (__half2float(y[p - 1])   + cb) + ar * (__half2float(y[p + 1])   + cb);
        const __half hv = __float2half_rn(v);
        nn[(size_t)c * HW + p] = hv;
        const float vr = __half2float(hv);    // stats from stored (rounded) value
        lsum += vr; lsq += vr * vr;
    }

    red[tid] = lsum; __syncthreads();
    for (int s = 128; s > 0; s >>= 1) { if (tid < s) red[tid] += red[tid + s]; __syncthreads(); }
    if (tid == 0) d_part[blk * 2] = (double)red[0];
    __syncthreads();
    red[tid] = lsq; __syncthreads();
    for (int s = 128; s > 0; s >>= 1) { if (tid < s) red[tid] += red[tid + s]; __syncthreads(); }
    if (tid == 0) d_part[blk * 2 + 1] = (double)red[0];

    // Last-block GroupNorm finalize (threadfence-reduction pattern).
    __shared__ unsigned isLast;
    __threadfence();
    if (tid == 0) isLast = (atomicAdd(&d_count, 1u) == 4095u) ? 1u : 0u;
    __syncthreads();
    if (isLast) {
        __threadfence();
        __shared__ double rs[256], rq[256];
        for (int bb = 0; bb < Bd; bb++) {
            double s = 0.0, q = 0.0;
            for (int i = tid; i < 2048; i += 256) {
                s += d_part[(bb * 2048 + i) * 2];
                q += d_part[(bb * 2048 + i) * 2 + 1];
            }
            rs[tid] = s; rq[tid] = q; __syncthreads();
            for (int st = 128; st > 0; st >>= 1) {
                if (tid < st) { rs[tid] += rs[tid + st]; rq[tid] += rq[tid + st]; }
                __syncthreads();
            }
            if (tid == 0) {
                const double N = (double)Cd * HW;
                const double mu = rs[0] / N;
                const double var = rq[0] / N - mu * mu;
                d_stats[bb * 2]     = (float)mu;
                d_stats[bb * 2 + 1] = (float)rsqrt(var + EPSV);
            }
            __syncthreads();
        }
        if (tid == 0) d_count = 0;   // self-reset for next graph replay
    }
}

// ---------------------------------------------------------------------------
// Epilogue: out = relu((nn - mu)*rsig*gamma + beta) + x   (nn is fp16)
// ---------------------------------------------------------------------------
__global__ void __launch_bounds__(256) final_kernel(const float* __restrict__ x,
                                                    const float* __restrict__ gamma,
                                                    const float* __restrict__ beta,
                                                    float* __restrict__ out) {
    const int idx4 = blockIdx.x * blockDim.x + threadIdx.x;
    const int b = idx4 >> 21;
    const int c = (idx4 >> 14) & 127;
    const float mu = d_stats[b * 2], rs = d_stats[b * 2 + 1];
    const float g  = gamma[c] * rs;
    const float bt = beta[c] - mu * g;
    const uint2 hv = ((const uint2*)d_nn)[idx4];
    const float2 v01 = __half22float2(*(const __half2*)&hv.x);
    const float2 v23 = __half22float2(*(const __half2*)&hv.y);
    const float4 xv = ((const float4*)x)[idx4];
    float4 o;
    o.x = fmaxf(v01.x * g + bt, 0.f) + xv.x;
    o.y = fmaxf(v01.y * g + bt, 0.f) + xv.y;
    o.z = fmaxf(v23.x * g + bt, 0.f) + xv.z;
    o.w = fmaxf(v23.y * g + bt, 0.f) + xv.w;
    ((float4*)out)[idx4] = o;
}

// ---------------------------------------------------------------------------
// Launch
// ---------------------------------------------------------------------------
extern "C" void kernel_launch(void* const* d_in, const int* in_sizes, int n_in,
                              void* d_out, int out_size) {
    const float* x     = (const float*)d_in[0];
    const float* Wn    = (const float*)d_in[1];
    const float* bn    = (const float*)d_in[2];
    const float* We    = (const float*)d_in[3];
    const float* be    = (const float*)d_in[4];
    const float* Wa1   = (const float*)d_in[5];
    const float* ba1   = (const float*)d_in[6];
    const float* Wa2   = (const float*)d_in[7];
    const float* ba2   = (const float*)d_in[8];
    const float* Wu    = (const float*)d_in[9];
    const float* bu    = (const float*)d_in[10];
    const float* gamma = (const float*)d_in[11];
    const float* beta  = (const float*)d_in[12];
    float* out = (float*)d_out;

    cudaFuncSetAttribute(mma_kernel, cudaFuncAttributeMaxDynamicSharedMemorySize, SMEM_SZ);

    prep_kernel<<<GR + 1, 128>>>(Wn, We, Wa1, Wu, bn, be, bu);
    mma_kernel<<<NCTA, 320, SMEM_SZ>>>(x);
    combine_kernel<<<4096, 256>>>(ba1, Wa2, ba2);
    final_kernel<<<(Bd * Cd * HW / 4) / 256, 256>>>(x, gamma, beta, out);
}

// round 9
// speedup vs baseline: 1.9936x; 1.0659x over previous
#include <cuda_runtime.h>
#include <cuda_fp16.h>
#include <math.h>
#include <stdint.h>

// Problem constants
#define Bd   2
#define Cd   128
#define HW   65536          // 256*256
#define GR   320            // stacked M (z 0..127, y 128..255, u 256..271, t 272..287, pad..319)
#define GUSE 288            // rows actually stored/used
#define EPSV 1e-5
#define NTILE 2048          // 64-pixel tiles (1024 per batch * 2 batches)
#define NCTA  152           // persistent CTAs (1 per GB300 SM)

// ---------------------------------------------------------------------------
// Scratch (device globals: allocation-free kernel_launch)
// ---------------------------------------------------------------------------
__device__ __half d_Wh[GR * 128];               // fp16 stacked weights
__device__ float  d_cA[128];
__device__ float  d_cB[128];
__device__ __half d_G[(size_t)Bd * GR * HW];    // fp16 stacked GEMM output
__device__ __half d_nn[(size_t)Bd * Cd * HW];   // fp16 pre-norm activations
__device__ double d_part[4096 * 2];
__device__ float  d_stats[4];
__device__ unsigned d_count = 0;

__device__ __forceinline__ uint32_t smem_u32(const void* p) {
    uint32_t a;
    asm("{ .reg .u64 t; cvta.to.shared.u64 t, %1; cvt.u32.u64 %0, t; }" : "=r"(a) : "l"(p));
    return a;
}
__device__ __forceinline__ void ldsm_x4(uint32_t* r, uint32_t addr) {
    asm volatile("ldmatrix.sync.aligned.m8n8.x4.shared.b16 {%0,%1,%2,%3}, [%4];"
                 : "=r"(r[0]), "=r"(r[1]), "=r"(r[2]), "=r"(r[3]) : "r"(addr));
}
__device__ __forceinline__ void ldsm_x4_t(uint32_t* r, uint32_t addr) {
    asm volatile("ldmatrix.sync.aligned.m8n8.x4.trans.shared.b16 {%0,%1,%2,%3}, [%4];"
                 : "=r"(r[0]), "=r"(r[1]), "=r"(r[2]), "=r"(r[3]) : "r"(addr));
}
__device__ __forceinline__ void mma_f16(float* d, const uint32_t* a, const uint32_t* b) {
    asm volatile("mma.sync.aligned.m16n8k16.row.col.f32.f16.f16.f32 "
                 "{%0,%1,%2,%3}, {%4,%5,%6,%7}, {%8,%9}, {%0,%1,%2,%3};"
                 : "+f"(d[0]), "+f"(d[1]), "+f"(d[2]), "+f"(d[3])
                 : "r"(a[0]), "r"(a[1]), "r"(a[2]), "r"(a[3]), "r"(b[0]), "r"(b[1]));
}

// ---------------------------------------------------------------------------
// Prep: stacked fp16 weights + folded biases.
// rows 0..127: Wu[:, :128]@Wn ; 128..255: Wu[:,128:]@We ; 256..271: Wa1 u ;
// 272..287: Wa1 t ; 288..319: zero pad. Block GR: cA/cB.
// ---------------------------------------------------------------------------
__global__ void prep_kernel(const float* __restrict__ Wn, const float* __restrict__ We,
                            const float* __restrict__ Wa1, const float* __restrict__ Wu,
                            const float* __restrict__ bn, const float* __restrict__ be,
                            const float* __restrict__ bu) {
    __shared__ float wbuf[128];
    const int r = blockIdx.x;
    const int c = threadIdx.x;
    if (r < GR) {
        float v = 0.f;
        if (r < 128) {
            wbuf[c] = Wu[r * 256 + c];
            __syncthreads();
            #pragma unroll 8
            for (int k = 0; k < 128; k++) v += wbuf[k] * Wn[k * 128 + c];
        } else if (r < 256) {
            wbuf[c] = Wu[(r - 128) * 256 + 128 + c];
            __syncthreads();
            #pragma unroll 8
            for (int k = 0; k < 128; k++) v += wbuf[k] * We[k * 128 + c];
        } else if (r < 272) {
            v = Wa1[(r - 256) * 256 + c];
        } else if (r < 288) {
            v = Wa1[(r - 272) * 256 + 128 + c];
        }
        d_Wh[r * 128 + c] = __float2half_rn(v);
    } else {
        float a = bu[c], bb = 0.f;
        for (int k = 0; k < 128; k++) {
            a  += Wu[c * 256 + k]       * bn[k];
            bb += Wu[c * 256 + 128 + k] * be[k];
        }
        d_cA[c] = a;
        d_cB[c] = bb;
    }
}

// ---------------------------------------------------------------------------
// Persistent tensor-core GEMM (mma.sync fp16, X split hi/lo, 2 products).
// 152 CTAs x 512 threads (16 warps: 4m x 4n, warp tile 80x16).
// SMEM: Wh 80K | X stage0 (hi16K+lo16K) | X stage1 = 144 KB.
// ---------------------------------------------------------------------------
#define OFF_W   0
#define OFF_X   81920
#define XSTAGE  32768
#define SMEM_SZ 147456

__global__ void __launch_bounds__(512, 1) mma_kernel(const float* __restrict__ x) {
    extern __shared__ __align__(16) uint8_t smem[];
    const uint32_t sb = smem_u32(smem);
    const int tid = threadIdx.x, lane = tid & 31, w = tid >> 5;
    const int wm = w >> 2, wn = w & 3;          // 4 m-warps (80 rows) x 4 n-warps (16 cols)
    const int miN = (wm == 3) ? 3 : 5;          // wm=3 covers 240..319; skip >=288

    // Load W once (fp16), swizzled [m][k]: row = 256B, 16 uint4/row.
    for (int i = tid; i < 5120; i += 512) {
        const int m = i >> 4, q = i & 15;
        const uint32_t off = m * 256 + ((q * 16) ^ ((m & 7) * 16));
        *(uint4*)(smem + OFF_W + off) = ((const uint4*)d_Wh)[i];
    }

    const int lr = (lane & 7) + ((lane >> 3) & 1) * 8;
    const int lc = (lane >> 4) * 8;

    // Register prefetch of first tile's X block (exactly 4 float4/thread).
    float4 xpre[4];
    const int t0 = blockIdx.x;
    {
        const int b = t0 >> 10, p0 = (t0 & 1023) << 6;
        const float* Xg = x + (size_t)b * Cd * HW + p0;
        #pragma unroll
        for (int j = 0; j < 4; j++) {
            const int i = tid + j * 512;
            xpre[j] = *(const float4*)(Xg + (size_t)(i >> 4) * HW + (i & 15) * 4);
        }
    }

    int stage = 0;
    for (int t = t0; t < NTILE; t += NCTA) {
        const int b = t >> 10, p0 = (t & 1023) << 6;
        const uint32_t xh = OFF_X + stage * XSTAGE;
        const uint32_t xl = xh + 16384;

        // Convert prefetched fp32 -> fp16 hi/lo into this stage.
        #pragma unroll
        for (int j = 0; j < 4; j++) {
            const float4 v = xpre[j];
            const int i = tid + j * 512;
            const int k = i >> 4, n0 = (i & 15) * 4;
            __half2 h01, h23, l01, l23;
            h01.x = __float2half_rn(v.x); l01.x = __float2half_rn(v.x - __half2float(h01.x));
            h01.y = __float2half_rn(v.y); l01.y = __float2half_rn(v.y - __half2float(h01.y));
            h23.x = __float2half_rn(v.z); l23.x = __float2half_rn(v.z - __half2float(h23.x));
            h23.y = __float2half_rn(v.w); l23.y = __float2half_rn(v.w - __half2float(h23.y));
            const uint32_t off = k * 128 + ((n0 * 2) ^ ((k & 7) * 16));
            uint2 hp, lp;
            hp.x = *(uint32_t*)&h01; hp.y = *(uint32_t*)&h23;
            lp.x = *(uint32_t*)&l01; lp.y = *(uint32_t*)&l23;
            *(uint2*)(smem + xh + off) = hp;
            *(uint2*)(smem + xl + off) = lp;
        }
        __syncthreads();

        // Prefetch next tile's X (overlaps with compute below).
        const int tn = t + NCTA;
        if (tn < NTILE) {
            const int bn_ = tn >> 10, pn = (tn & 1023) << 6;
            const float* Xg = x + (size_t)bn_ * Cd * HW + pn;
            #pragma unroll
            for (int j = 0; j < 4; j++) {
                const int i = tid + j * 512;
                xpre[j] = *(const float4*)(Xg + (size_t)(i >> 4) * HW + (i & 15) * 4);
            }
        }

        // Compute: K loop over 8 chunks of 16.
        float acc[5][2][4] = {};
        #pragma unroll 1
        for (int kk = 0; kk < 8; kk++) {
            const int k0 = kk * 16;
            uint32_t ah[5][4];
            #pragma unroll
            for (int mi = 0; mi < 5; mi++) {
                if (mi >= miN) break;
                const int row = wm * 80 + mi * 16 + lr;
                const int col = k0 + lc;
                const uint32_t off = row * 256 + ((col * 2) ^ ((row & 7) * 16));
                ldsm_x4(ah[mi], sb + OFF_W + off);
            }
            uint32_t bh[4], bl[4];
            {
                const int kr = k0 + lr;
                const int nc = wn * 16 + lc;
                const uint32_t off = kr * 128 + ((nc * 2) ^ ((kr & 7) * 16));
                ldsm_x4_t(bh, sb + xh + off);
                ldsm_x4_t(bl, sb + xl + off);
            }
            #pragma unroll
            for (int mi = 0; mi < 5; mi++) {
                if (mi >= miN) break;
                #pragma unroll
                for (int ni = 0; ni < 2; ni++) {
                    mma_f16(acc[mi][ni], ah[mi], &bh[ni * 2]);   // W·Xhi
                    mma_f16(acc[mi][ni], ah[mi], &bl[ni * 2]);   // W·Xlo
                }
            }
        }

        // Store G rows < 288 as fp16 (half2 pairs).
        __half* Gout = d_G + (size_t)b * GR * HW;
        const int cbase = p0 + wn * 16 + (lane & 3) * 2;
        #pragma unroll
        for (int mi = 0; mi < 5; mi++) {
            const int mb = wm * 80 + mi * 16;
            if (mb >= GUSE) break;
            const int r0 = mb + (lane >> 2);
            __half* g0 = Gout + (size_t)r0 * HW + cbase;
            __half* g1 = g0 + (size_t)8 * HW;
            #pragma unroll
            for (int ni = 0; ni < 2; ni++) {
                *(__half2*)(g0 + ni * 8) = __floats2half2_rn(acc[mi][ni][0], acc[mi][ni][1]);
                *(__half2*)(g1 + ni * 8) = __floats2half2_rn(acc[mi][ni][2], acc[mi][ni][3]);
            }
        }
        stage ^= 1;
    }
}

// ---------------------------------------------------------------------------
// Combine: attention gates + gated aggregation + partial GN sums (fp16 G/nn).
// Shuffle-based deterministic reduction. Last block computes per-batch stats.
// ---------------------------------------------------------------------------
__global__ void __launch_bounds__(256) combine_kernel(const float* __restrict__ ba1,
                                                      const float* __restrict__ Wa2,
                                                      const float* __restrict__ ba2) {
    const int blk = blockIdx.x;
    const int b   = blk >> 11;
    const int p0  = (blk & 2047) << 5;
    const __half* __restrict__ G = d_G + (size_t)b * GR * HW;
    __half* __restrict__ nn = d_nn + (size_t)b * Cd * HW;

    __shared__ float a_s[4][32];
    __shared__ float cA_s[128], cB_s[128];
    __shared__ float reds[8], redq[8];

    const int tid = threadIdx.x;
    if (tid < 128) { cA_s[tid] = d_cA[tid]; cB_s[tid] = d_cB[tid]; }

    const int hrow = p0 >> 8;

    if (tid < 128) {
        const int dir = tid >> 5, px = tid & 31;
        const int p = p0 + px, wcol = p & 255;
        int off; bool valid;
        switch (dir) {
            case 0:  off = -256; valid = (hrow > 0);    break;
            case 1:  off =  256; valid = (hrow < 255);  break;
            case 2:  off =   -1; valid = (wcol > 0);    break;
            default: off =    1; valid = (wcol < 255);  break;
        }
        float a = 0.f;
        if (valid) {
            float logit = ba2[0];
            const __half* Gu = G + 256 * HW + p;
            const __half* Gt = G + 272 * HW + p + off;
            #pragma unroll
            for (int i = 0; i < 16; i++) {
                float hv = __half2float(Gu[i * HW]) + __half2float(Gt[i * HW]) + ba1[i];
                hv = hv > 0.f ? hv : 0.2f * hv;
                logit += Wa2[i] * hv;
            }
            a = 1.f / (1.f + expf(-logit));
        }
        a_s[dir][px] = a;
    }
    __syncthreads();

    const int wq = tid >> 5, lane = tid & 31;
    const int p = p0 + lane;
    const float au = a_s[0][lane], ad = a_s[1][lane];
    const float al = a_s[2][lane], ar = a_s[3][lane];

    float lsum = 0.f, lsq = 0.f;
    #pragma unroll
    for (int ci = 0; ci < 16; ci++) {
        const int c = (wq << 4) + ci;
        const __half* z = G + (size_t)c * HW;
        const __half* y = G + (size_t)(128 + c) * HW;
        const float cb = cB_s[c];
        float v = __half2float(z[p]) + cA_s[c]
                + au * (__half2float(y[p - 256]) + cb) + ad * (__half2float(y[p + 256]) + cb)
                + al * (__half2float(y[p - 1])   + cb) + ar * (__half2float(y[p + 1])   + cb);
        const __half hv = __float2half_rn(v);
        nn[(size_t)c * HW + p] = hv;
        const float vr = __half2float(hv);    // stats from stored (rounded) value
        lsum += vr; lsq += vr * vr;
    }

    // Deterministic butterfly + fixed-order cross-warp reduction.
    #pragma unroll
    for (int s = 16; s > 0; s >>= 1) {
        lsum += __shfl_xor_sync(0xFFFFFFFFu, lsum, s);
        lsq  += __shfl_xor_sync(0xFFFFFFFFu, lsq,  s);
    }
    if (lane == 0) { reds[wq] = lsum; redq[wq] = lsq; }
    __syncthreads();
    if (tid == 0) {
        float s = 0.f, q = 0.f;
        #pragma unroll
        for (int i = 0; i < 8; i++) { s += reds[i]; q += redq[i]; }
        d_part[blk * 2] = (double)s;
        d_part[blk * 2 + 1] = (double)q;
    }

    // Last-block GroupNorm finalize (threadfence-reduction pattern).
    __shared__ unsigned isLast;
    __threadfence();
    if (tid == 0) isLast = (atomicAdd(&d_count, 1u) == 4095u) ? 1u : 0u;
    __syncthreads();
    if (isLast) {
        __threadfence();
        __shared__ double rs[256], rq[256];
        for (int bb = 0; bb < Bd; bb++) {
            double s = 0.0, q = 0.0;
            for (int i = tid; i < 2048; i += 256) {
                s += d_part[(bb * 2048 + i) * 2];
                q += d_part[(bb * 2048 + i) * 2 + 1];
            }
            rs[tid] = s; rq[tid] = q; __syncthreads();
            for (int st = 128; st > 0; st >>= 1) {
                if (tid < st) { rs[tid] += rs[tid + st]; rq[tid] += rq[tid + st]; }
                __syncthreads();
            }
            if (tid == 0) {
                const double N = (double)Cd * HW;
                const double mu = rs[0] / N;
                const double var = rq[0] / N - mu * mu;
                d_stats[bb * 2]     = (float)mu;
                d_stats[bb * 2 + 1] = (float)rsqrt(var + EPSV);
            }
            __syncthreads();
        }
        if (tid == 0) d_count = 0;   // self-reset for next graph replay
    }
}

// ---------------------------------------------------------------------------
// Epilogue: out = relu((nn - mu)*rsig*gamma + beta) + x   (nn is fp16)
// ---------------------------------------------------------------------------
__global__ void __launch_bounds__(256) final_kernel(const float* __restrict__ x,
                                                    const float* __restrict__ gamma,
                                                    const float* __restrict__ beta,
                                                    float* __restrict__ out) {
    const int idx4 = blockIdx.x * blockDim.x + threadIdx.x;
    const int b = idx4 >> 21;
    const int c = (idx4 >> 14) & 127;
    const float mu = d_stats[b * 2], rs = d_stats[b * 2 + 1];
    const float g  = gamma[c] * rs;
    const float bt = beta[c] - mu * g;
    const uint2 hv = ((const uint2*)d_nn)[idx4];
    const float2 v01 = __half22float2(*(const __half2*)&hv.x);
    const float2 v23 = __half22float2(*(const __half2*)&hv.y);
    const float4 xv = ((const float4*)x)[idx4];
    float4 o;
    o.x = fmaxf(v01.x * g + bt, 0.f) + xv.x;
    o.y = fmaxf(v01.y * g + bt, 0.f) + xv.y;
    o.z = fmaxf(v23.x * g + bt, 0.f) + xv.z;
    o.w = fmaxf(v23.y * g + bt, 0.f) + xv.w;
    ((float4*)out)[idx4] = o;
}

// ---------------------------------------------------------------------------
// Launch
// ---------------------------------------------------------------------------
extern "C" void kernel_launch(void* const* d_in, const int* in_sizes, int n_in,
                              void* d_out, int out_size) {
    const float* x     = (const float*)d_in[0];
    const float* Wn    = (const float*)d_in[1];
    const float* bn    = (const float*)d_in[2];
    const float* We    = (const float*)d_in[3];
    const float* be    = (const float*)d_in[4];
    const float* Wa1   = (const float*)d_in[5];
    const float* ba1   = (const float*)d_in[6];
    const float* Wa2   = (const float*)d_in[7];
    const float* ba2   = (const float*)d_in[8];
    const float* Wu    = (const float*)d_in[9];
    const float* bu    = (const float*)d_in[10];
    const float* gamma = (const float*)d_in[11];
    const float* beta  = (const float*)d_in[12];
    float* out = (float*)d_out;

    cudaFuncSetAttribute(mma_kernel, cudaFuncAttributeMaxDynamicSharedMemorySize, SMEM_SZ);

    prep_kernel<<<GR + 1, 128>>>(Wn, We, Wa1, Wu, bn, be, bu);
    mma_kernel<<<NCTA, 512, SMEM_SZ>>>(x);
    combine_kernel<<<4096, 256>>>(ba1, Wa2, ba2);
    final_kernel<<<(Bd * Cd * HW / 4) / 256, 256>>>(x, gamma, beta, out);
}

// round 10
// speedup vs baseline: 2.5915x; 1.2999x over previous
#include <cuda_runtime.h>
#include <cuda_fp16.h>
#include <math.h>
#include <stdint.h>

// Problem constants
#define Bd   2
#define Cd   128
#define HW   65536          // 256*256
#define GR   320            // stacked M (z 0..127, y 128..255, u 256..271, t 272..287, pad..319)
#define GUSE 288            // rows actually stored/used
#define EPSV 1e-5
#define NTILE 2048          // 64-pixel tiles (1024 per batch * 2 batches)
#define NCTA  152           // persistent CTAs (1 per GB300 SM)

// ---------------------------------------------------------------------------
// Scratch (device globals: allocation-free kernel_launch)
// ---------------------------------------------------------------------------
__device__ __half d_Wh[GR * 128];               // fp16 stacked weights
__device__ float  d_cA[128];
__device__ float  d_cB[128];
__device__ __half d_G[(size_t)Bd * GR * HW];    // fp16 stacked GEMM output
__device__ __half d_nn[(size_t)Bd * Cd * HW];   // fp16 pre-norm activations
__device__ double d_part[2048 * 2];
__device__ float  d_stats[4];
__device__ unsigned d_count = 0;

__device__ __forceinline__ uint32_t smem_u32(const void* p) {
    uint32_t a;
    asm("{ .reg .u64 t; cvta.to.shared.u64 t, %1; cvt.u32.u64 %0, t; }" : "=r"(a) : "l"(p));
    return a;
}
__device__ __forceinline__ void ldsm_x4(uint32_t* r, uint32_t addr) {
    asm volatile("ldmatrix.sync.aligned.m8n8.x4.shared.b16 {%0,%1,%2,%3}, [%4];"
                 : "=r"(r[0]), "=r"(r[1]), "=r"(r[2]), "=r"(r[3]) : "r"(addr));
}
__device__ __forceinline__ void ldsm_x4_t(uint32_t* r, uint32_t addr) {
    asm volatile("ldmatrix.sync.aligned.m8n8.x4.trans.shared.b16 {%0,%1,%2,%3}, [%4];"
                 : "=r"(r[0]), "=r"(r[1]), "=r"(r[2]), "=r"(r[3]) : "r"(addr));
}
__device__ __forceinline__ void mma_f16(float* d, const uint32_t* a, const uint32_t* b) {
    asm volatile("mma.sync.aligned.m16n8k16.row.col.f32.f16.f16.f32 "
                 "{%0,%1,%2,%3}, {%4,%5,%6,%7}, {%8,%9}, {%0,%1,%2,%3};"
                 : "+f"(d[0]), "+f"(d[1]), "+f"(d[2]), "+f"(d[3])
                 : "r"(a[0]), "r"(a[1]), "r"(a[2]), "r"(a[3]), "r"(b[0]), "r"(b[1]));
}

// ---------------------------------------------------------------------------
// Prep: stacked fp16 weights + folded biases.
// ---------------------------------------------------------------------------
__global__ void prep_kernel(const float* __restrict__ Wn, const float* __restrict__ We,
                            const float* __restrict__ Wa1, const float* __restrict__ Wu,
                            const float* __restrict__ bn, const float* __restrict__ be,
                            const float* __restrict__ bu) {
    __shared__ float wbuf[128];
    const int r = blockIdx.x;
    const int c = threadIdx.x;
    if (r < GR) {
        float v = 0.f;
        if (r < 128) {
            wbuf[c] = Wu[r * 256 + c];
            __syncthreads();
            #pragma unroll 8
            for (int k = 0; k < 128; k++) v += wbuf[k] * Wn[k * 128 + c];
        } else if (r < 256) {
            wbuf[c] = Wu[(r - 128) * 256 + 128 + c];
            __syncthreads();
            #pragma unroll 8
            for (int k = 0; k < 128; k++) v += wbuf[k] * We[k * 128 + c];
        } else if (r < 272) {
            v = Wa1[(r - 256) * 256 + c];
        } else if (r < 288) {
            v = Wa1[(r - 272) * 256 + 128 + c];
        }
        d_Wh[r * 128 + c] = __float2half_rn(v);
    } else {
        float a = bu[c], bb = 0.f;
        for (int k = 0; k < 128; k++) {
            a  += Wu[c * 256 + k]       * bn[k];
            bb += Wu[c * 256 + 128 + k] * be[k];
        }
        d_cA[c] = a;
        d_cB[c] = bb;
    }
}

// ---------------------------------------------------------------------------
// Persistent tensor-core GEMM (mma.sync fp16, X split hi/lo, 2 products).
// 152 CTAs x 512 threads (16 warps: 4m x 4n, warp tile 80x16).
// Epilogue staged via SMEM: 2 passes of 144 rows, row stride 144 B
// (bank = idx*4 + c, conflict-free), warp stores whole 128B rows.
// SMEM: Wh 80K | X stage0 (hi16K+lo16K) | X stage1 = 144 KB.
// ---------------------------------------------------------------------------
#define OFF_W   0
#define OFF_X   81920
#define XSTAGE  32768
#define EPSTRIDE 144         // bytes per staged row (36 words: idx*4+c banks)
#define SMEM_SZ 147456

__global__ void __launch_bounds__(512, 1) mma_kernel(const float* __restrict__ x) {
    extern __shared__ __align__(16) uint8_t smem[];
    const uint32_t sb = smem_u32(smem);
    const int tid = threadIdx.x, lane = tid & 31, w = tid >> 5;
    const int wm = w >> 2, wn = w & 3;          // 4 m-warps (80 rows) x 4 n-warps (16 cols)
    const int miN = (wm == 3) ? 3 : 5;          // wm=3 covers 240..319; skip >=288

    // Load W once (fp16), swizzled [m][k]: row = 256B, 16 uint4/row.
    for (int i = tid; i < 5120; i += 512) {
        const int m = i >> 4, q = i & 15;
        const uint32_t off = m * 256 + ((q * 16) ^ ((m & 7) * 16));
        *(uint4*)(smem + OFF_W + off) = ((const uint4*)d_Wh)[i];
    }

    const int lr = (lane & 7) + ((lane >> 3) & 1) * 8;
    const int lc = (lane >> 4) * 8;

    // Register prefetch of first tile's X block (exactly 4 float4/thread).
    float4 xpre[4];
    const int t0 = blockIdx.x;
    {
        const int b = t0 >> 10, p0 = (t0 & 1023) << 6;
        const float* Xg = x + (size_t)b * Cd * HW + p0;
        #pragma unroll
        for (int j = 0; j < 4; j++) {
            const int i = tid + j * 512;
            xpre[j] = *(const float4*)(Xg + (size_t)(i >> 4) * HW + (i & 15) * 4);
        }
    }

    int stage = 0;
    for (int t = t0; t < NTILE; t += NCTA) {
        const int b = t >> 10, p0 = (t & 1023) << 6;
        const uint32_t xh = OFF_X + stage * XSTAGE;
        const uint32_t xl = xh + 16384;

        // Convert prefetched fp32 -> fp16 hi/lo into this stage.
        #pragma unroll
        for (int j = 0; j < 4; j++) {
            const float4 v = xpre[j];
            const int i = tid + j * 512;
            const int k = i >> 4, n0 = (i & 15) * 4;
            __half2 h01, h23, l01, l23;
            h01.x = __float2half_rn(v.x); l01.x = __float2half_rn(v.x - __half2float(h01.x));
            h01.y = __float2half_rn(v.y); l01.y = __float2half_rn(v.y - __half2float(h01.y));
            h23.x = __float2half_rn(v.z); l23.x = __float2half_rn(v.z - __half2float(h23.x));
            h23.y = __float2half_rn(v.w); l23.y = __float2half_rn(v.w - __half2float(h23.y));
            const uint32_t off = k * 128 + ((n0 * 2) ^ ((k & 7) * 16));
            uint2 hp, lp;
            hp.x = *(uint32_t*)&h01; hp.y = *(uint32_t*)&h23;
            lp.x = *(uint32_t*)&l01; lp.y = *(uint32_t*)&l23;
            *(uint2*)(smem + xh + off) = hp;
            *(uint2*)(smem + xl + off) = lp;
        }
        __syncthreads();

        // Prefetch next tile's X (overlaps with compute below).
        const int tn = t + NCTA;
        if (tn < NTILE) {
            const int bn_ = tn >> 10, pn = (tn & 1023) << 6;
            const float* Xg = x + (size_t)bn_ * Cd * HW + pn;
            #pragma unroll
            for (int j = 0; j < 4; j++) {
                const int i = tid + j * 512;
                xpre[j] = *(const float4*)(Xg + (size_t)(i >> 4) * HW + (i & 15) * 4);
            }
        }

        // Compute: K loop over 8 chunks of 16.
        float acc[5][2][4] = {};
        #pragma unroll 1
        for (int kk = 0; kk < 8; kk++) {
            const int k0 = kk * 16;
            uint32_t ah[5][4];
            #pragma unroll
            for (int mi = 0; mi < 5; mi++) {
                if (mi >= miN) break;
                const int row = wm * 80 + mi * 16 + lr;
                const int col = k0 + lc;
                const uint32_t off = row * 256 + ((col * 2) ^ ((row & 7) * 16));
                ldsm_x4(ah[mi], sb + OFF_W + off);
            }
            uint32_t bh[4], bl[4];
            {
                const int kr = k0 + lr;
                const int nc = wn * 16 + lc;
                const uint32_t off = kr * 128 + ((nc * 2) ^ ((kr & 7) * 16));
                ldsm_x4_t(bh, sb + xh + off);
                ldsm_x4_t(bl, sb + xl + off);
            }
            #pragma unroll
            for (int mi = 0; mi < 5; mi++) {
                if (mi >= miN) break;
                #pragma unroll
                for (int ni = 0; ni < 2; ni++) {
                    mma_f16(acc[mi][ni], ah[mi], &bh[ni * 2]);   // W·Xhi
                    mma_f16(acc[mi][ni], ah[mi], &bl[ni * 2]);   // W·Xlo
                }
            }
        }
        __syncthreads();   // all reads of this X stage done; reuse it for epilogue

        // Epilogue: 2 passes of 144 rows through SMEM, coalesced 128B row stores.
        __half* Gout = d_G + (size_t)b * GR * HW;
        const int ccol = wn * 16 + (lane & 3) * 2;
        #pragma unroll 1
        for (int pass = 0; pass < 2; pass++) {
            const int rbase = pass * 144;
            // stage accumulator fragments belonging to this pass
            #pragma unroll
            for (int mi = 0; mi < 5; mi++) {
                const int mb = wm * 80 + mi * 16;
                if (mb >= GUSE || mi >= miN) break;
                if ((mb >= rbase) && (mb < rbase + 144)) {
                    const int idx0 = mb - rbase + (lane >> 2);
                    #pragma unroll
                    for (int ni = 0; ni < 2; ni++) {
                        const uint32_t a0 = xh + idx0 * EPSTRIDE + (ccol + ni * 8) * 2;
                        *(__half2*)(smem + a0) =
                            __floats2half2_rn(acc[mi][ni][0], acc[mi][ni][1]);
                        *(__half2*)(smem + a0 + 8 * EPSTRIDE) =
                            __floats2half2_rn(acc[mi][ni][2], acc[mi][ni][3]);
                    }
                }
            }
            __syncthreads();
            // coalesced stores: each warp 9 rows, one 128B row per STG pass
            #pragma unroll
            for (int j = 0; j < 9; j++) {
                const int idx = w * 9 + j;             // 16*9 = 144 rows
                const uint32_t word = *(const uint32_t*)(smem + xh + idx * EPSTRIDE + lane * 4);
                *(uint32_t*)((__half*)Gout + (size_t)(rbase + idx) * HW + p0 + lane * 2) = word;
            }
            __syncthreads();
        }
        stage ^= 1;
    }
}

// ---------------------------------------------------------------------------
// Combine: 64-pixel blocks, half2 loads (full-sector). Gates: 256 threads =
// 4 dirs x 64 px. Aggregation: 8 warps x 16 channels, lane = pixel pair.
// Partial GN sums + fused last-block finalize. Deterministic.
// ---------------------------------------------------------------------------
__global__ void __launch_bounds__(256) combine_kernel(const float* __restrict__ ba1,
                                                      const float* __restrict__ Wa2,
                                                      const float* __restrict__ ba2) {
    const int blk = blockIdx.x;            // 0..2047
    const int b   = blk >> 10;
    const int p0  = (blk & 1023) << 6;     // 64-px tile, single image row
    const __half* __restrict__ G = d_G + (size_t)b * GR * HW;
    __half* __restrict__ nn = d_nn + (size_t)b * Cd * HW;

    __shared__ float a_s[4][64];
    __shared__ float cA_s[128], cB_s[128];
    __shared__ float reds[8], redq[8];

    const int tid = threadIdx.x;
    if (tid < 128) { cA_s[tid] = d_cA[tid]; cB_s[tid] = d_cB[tid]; }

    const int hrow = p0 >> 8;

    {   // gates: one per thread (dir, px)
        const int dir = tid >> 6, px = tid & 63;
        const int p = p0 + px, wcol = p & 255;
        int off; bool valid;
        switch (dir) {
            case 0:  off = -256; valid = (hrow > 0);    break;
            case 1:  off =  256; valid = (hrow < 255);  break;
            case 2:  off =   -1; valid = (wcol > 0);    break;
            default: off =    1; valid = (wcol < 255);  break;
        }
        float a = 0.f;
        if (valid) {
            float logit = ba2[0];
            const __half* Gu = G + 256 * HW + p;
            const __half* Gt = G + 272 * HW + p + off;
            #pragma unroll
            for (int i = 0; i < 16; i++) {
                float hv = __half2float(Gu[i * HW]) + __half2float(Gt[i * HW]) + ba1[i];
                hv = hv > 0.f ? hv : 0.2f * hv;
                logit += Wa2[i] * hv;
            }
            a = 1.f / (1.f + expf(-logit));
        }
        a_s[dir][px] = a;
    }
    __syncthreads();

    const int wq = tid >> 5, lane = tid & 31;
    const int q = p0 + 2 * lane;            // even pixel of pair
    const int px2 = 2 * lane;
    const float au0 = a_s[0][px2], au1 = a_s[0][px2 + 1];
    const float ad0 = a_s[1][px2], ad1 = a_s[1][px2 + 1];
    const float al0 = a_s[2][px2], al1 = a_s[2][px2 + 1];
    const float ar0 = a_s[3][px2], ar1 = a_s[3][px2 + 1];

    float lsum = 0.f, lsq = 0.f;
    #pragma unroll
    for (int ci = 0; ci < 16; ci++) {
        const int c = (wq << 4) + ci;
        const __half* z = G + (size_t)c * HW;
        const __half* y = G + (size_t)(128 + c) * HW;
        const float cb = cB_s[c];
        const float2 zv = __half22float2(*(const __half2*)(z + q));
        const float2 yu = __half22float2(*(const __half2*)(y + q - 256));
        const float2 yd = __half22float2(*(const __half2*)(y + q + 256));
        const float2 ym = __half22float2(*(const __half2*)(y + q));       // y[q], y[q+1]
        const float2 yl = __half22float2(*(const __half2*)(y + q - 2));   // y[q-2], y[q-1]
        const float2 yr = __half22float2(*(const __half2*)(y + q + 2));   // y[q+2], y[q+3]
        float v0 = zv.x + cA_s[c]
                 + au0 * (yu.x + cb) + ad0 * (yd.x + cb)
                 + al0 * (yl.y + cb) + ar0 * (ym.y + cb);
        float v1 = zv.y + cA_s[c]
                 + au1 * (yu.y + cb) + ad1 * (yd.y + cb)
                 + al1 * (ym.x + cb) + ar1 * (yr.x + cb);
        const __half2 hv = __floats2half2_rn(v0, v1);
        *(__half2*)(nn + (size_t)c * HW + q) = hv;
        const float2 vr = __half22float2(hv);   // stats from stored (rounded) values
        lsum += vr.x + vr.y;
        lsq  += vr.x * vr.x + vr.y * vr.y;
    }

    // Deterministic butterfly + fixed-order cross-warp reduction.
    #pragma unroll
    for (int s = 16; s > 0; s >>= 1) {
        lsum += __shfl_xor_sync(0xFFFFFFFFu, lsum, s);
        lsq  += __shfl_xor_sync(0xFFFFFFFFu, lsq,  s);
    }
    if (lane == 0) { reds[wq] = lsum; redq[wq] = lsq; }
    __syncthreads();
    if (tid == 0) {
        float s = 0.f, qv = 0.f;
        #pragma unroll
        for (int i = 0; i < 8; i++) { s += reds[i]; qv += redq[i]; }
        d_part[blk * 2] = (double)s;
        d_part[blk * 2 + 1] = (double)qv;
    }

    // Last-block GroupNorm finalize (threadfence-reduction pattern).
    __shared__ unsigned isLast;
    __threadfence();
    if (tid == 0) isLast = (atomicAdd(&d_count, 1u) == 2047u) ? 1u : 0u;
    __syncthreads();
    if (isLast) {
        __threadfence();
        __shared__ double rs[256], rq[256];
        for (int bb = 0; bb < Bd; bb++) {
            double s = 0.0, qd = 0.0;
            for (int i = tid; i < 1024; i += 256) {
                s  += d_part[(bb * 1024 + i) * 2];
                qd += d_part[(bb * 1024 + i) * 2 + 1];
            }
            rs[tid] = s; rq[tid] = qd; __syncthreads();
            for (int st = 128; st > 0; st >>= 1) {
                if (tid < st) { rs[tid] += rs[tid + st]; rq[tid] += rq[tid + st]; }
                __syncthreads();
            }
            if (tid == 0) {
                const double N = (double)Cd * HW;
                const double mu = rs[0] / N;
                const double var = rq[0] / N - mu * mu;
                d_stats[bb * 2]     = (float)mu;
                d_stats[bb * 2 + 1] = (float)rsqrt(var + EPSV);
            }
            __syncthreads();
        }
        if (tid == 0) d_count = 0;   // self-reset for next graph replay
    }
}

// ---------------------------------------------------------------------------
// Epilogue: out = relu((nn - mu)*rsig*gamma + beta) + x   (nn is fp16)
// ---------------------------------------------------------------------------
__global__ void __launch_bounds__(256) final_kernel(const float* __restrict__ x,
                                                    const float* __restrict__ gamma,
                                                    const float* __restrict__ beta,
                                                    float* __restrict__ out) {
    const int idx4 = blockIdx.x * blockDim.x + threadIdx.x;
    const int b = idx4 >> 21;
    const int c = (idx4 >> 14) & 127;
    const float mu = d_stats[b * 2], rs = d_stats[b * 2 + 1];
    const float g  = gamma[c] * rs;
    const float bt = beta[c] - mu * g;
    const uint2 hv = ((const uint2*)d_nn)[idx4];
    const float2 v01 = __half22float2(*(const __half2*)&hv.x);
    const float2 v23 = __half22float2(*(const __half2*)&hv.y);
    const float4 xv = ((const float4*)x)[idx4];
    float4 o;
    o.x = fmaxf(v01.x * g + bt, 0.f) + xv.x;
    o.y = fmaxf(v01.y * g + bt, 0.f) + xv.y;
    o.z = fmaxf(v23.x * g + bt, 0.f) + xv.z;
    o.w = fmaxf(v23.y * g + bt, 0.f) + xv.w;
    ((float4*)out)[idx4] = o;
}

// ---------------------------------------------------------------------------
// Launch
// ---------------------------------------------------------------------------
extern "C" void kernel_launch(void* const* d_in, const int* in_sizes, int n_in,
                              void* d_out, int out_size) {
    const float* x     = (const float*)d_in[0];
    const float* Wn    = (const float*)d_in[1];
    const float* bn    = (const float*)d_in[2];
    const float* We    = (const float*)d_in[3];
    const float* be    = (const float*)d_in[4];
    const float* Wa1   = (const float*)d_in[5];
    const float* ba1   = (const float*)d_in[6];
    const float* Wa2   = (const float*)d_in[7];
    const float* ba2   = (const float*)d_in[8];
    const float* Wu    = (const float*)d_in[9];
    const float* bu    = (const float*)d_in[10];
    const float* gamma = (const float*)d_in[11];
    const float* beta  = (const float*)d_in[12];
    float* out = (float*)d_out;

    cudaFuncSetAttribute(mma_kernel, cudaFuncAttributeMaxDynamicSharedMemorySize, SMEM_SZ);

    prep_kernel<<<GR + 1, 128>>>(Wn, We, Wa1, Wu, bn, be, bu);
    mma_kernel<<<NCTA, 512, SMEM_SZ>>>(x);
    combine_kernel<<<2048, 256>>>(ba1, Wa2, ba2);
    final_kernel<<<(Bd * Cd * HW / 4) / 256, 256>>>(x, gamma, beta, out);
}

// round 11
// speedup vs baseline: 2.9200x; 1.1268x over previous
#include <cuda_runtime.h>
#include <cuda_fp16.h>
#include <math.h>
#include <stdint.h>

// Problem constants
#define Bd   2
#define Cd   128
#define HW   65536          // 256*256
#define GR   320            // stacked M (z 0..127, y 128..255, u 256..271, t 272..287, pad..319)
#define GUSE 288            // rows actually stored/used
#define EPSV 1e-5
#define NTILE 2048          // 64-pixel tiles (1024 per batch * 2 batches)
#define NCTA  152           // persistent CTAs (1 per GB300 SM)

// ---------------------------------------------------------------------------
// Scratch (device globals: allocation-free kernel_launch)
// ---------------------------------------------------------------------------
__device__ __half d_Wh[GR * 128];               // fp16 stacked weights
__device__ float  d_cA[128];
__device__ float  d_cB[128];
__device__ __half d_G[(size_t)Bd * GR * HW];    // fp16 stacked GEMM output
__device__ __half d_nn[(size_t)Bd * Cd * HW];   // fp16 pre-norm activations
__device__ double d_part[2048 * 2];
__device__ float  d_stats[4];
__device__ unsigned d_count = 0;

__device__ __forceinline__ uint32_t smem_u32(const void* p) {
    uint32_t a;
    asm("{ .reg .u64 t; cvta.to.shared.u64 t, %1; cvt.u32.u64 %0, t; }" : "=r"(a) : "l"(p));
    return a;
}
__device__ __forceinline__ void ldsm_x4(uint32_t* r, uint32_t addr) {
    asm volatile("ldmatrix.sync.aligned.m8n8.x4.shared.b16 {%0,%1,%2,%3}, [%4];"
                 : "=r"(r[0]), "=r"(r[1]), "=r"(r[2]), "=r"(r[3]) : "r"(addr));
}
__device__ __forceinline__ void ldsm_x4_t(uint32_t* r, uint32_t addr) {
    asm volatile("ldmatrix.sync.aligned.m8n8.x4.trans.shared.b16 {%0,%1,%2,%3}, [%4];"
                 : "=r"(r[0]), "=r"(r[1]), "=r"(r[2]), "=r"(r[3]) : "r"(addr));
}
__device__ __forceinline__ void mma_f16(float* d, const uint32_t* a, const uint32_t* b) {
    asm volatile("mma.sync.aligned.m16n8k16.row.col.f32.f16.f16.f32 "
                 "{%0,%1,%2,%3}, {%4,%5,%6,%7}, {%8,%9}, {%0,%1,%2,%3};"
                 : "+f"(d[0]), "+f"(d[1]), "+f"(d[2]), "+f"(d[3])
                 : "r"(a[0]), "r"(a[1]), "r"(a[2]), "r"(a[3]), "r"(b[0]), "r"(b[1]));
}

// ---------------------------------------------------------------------------
// Prep: stacked fp16 weights + folded biases.
// ---------------------------------------------------------------------------
__global__ void prep_kernel(const float* __restrict__ Wn, const float* __restrict__ We,
                            const float* __restrict__ Wa1, const float* __restrict__ Wu,
                            const float* __restrict__ bn, const float* __restrict__ be,
                            const float* __restrict__ bu) {
    __shared__ float wbuf[128];
    const int r = blockIdx.x;
    const int c = threadIdx.x;
    if (r < GR) {
        float v = 0.f;
        if (r < 128) {
            wbuf[c] = Wu[r * 256 + c];
            __syncthreads();
            #pragma unroll 8
            for (int k = 0; k < 128; k++) v += wbuf[k] * Wn[k * 128 + c];
        } else if (r < 256) {
            wbuf[c] = Wu[(r - 128) * 256 + 128 + c];
            __syncthreads();
            #pragma unroll 8
            for (int k = 0; k < 128; k++) v += wbuf[k] * We[k * 128 + c];
        } else if (r < 272) {
            v = Wa1[(r - 256) * 256 + c];
        } else if (r < 288) {
            v = Wa1[(r - 272) * 256 + 128 + c];
        }
        d_Wh[r * 128 + c] = __float2half_rn(v);
    } else {
        float a = bu[c], bb = 0.f;
        for (int k = 0; k < 128; k++) {
            a  += Wu[c * 256 + k]       * bn[k];
            bb += Wu[c * 256 + 128 + k] * be[k];
        }
        d_cA[c] = a;
        d_cB[c] = bb;
    }
}

// ---------------------------------------------------------------------------
// Persistent tensor-core GEMM (mma.sync fp16, single product).
// 152 CTAs x 512 threads (16 warps: 4m x 4n, warp tile 80x16).
// Single X buffer (16 KB); epilogue stages all 288 rows (41.5 KB, reusing the
// X region after compute) and each warp stores 18 full 128B rows. 4 barriers
// per tile.  SMEM: Wh 80K | X/epilogue 42K = 125 KB.
// ---------------------------------------------------------------------------
#define OFF_W   0
#define OFF_X   81920
#define EPSTRIDE 144         // bytes per staged row (36 words: 4r+c banks, conflict-free)
#define SMEM_SZ 124928

__global__ void __launch_bounds__(512, 1) mma_kernel(const float* __restrict__ x) {
    extern __shared__ __align__(16) uint8_t smem[];
    const uint32_t sb = smem_u32(smem);
    const int tid = threadIdx.x, lane = tid & 31, w = tid >> 5;
    const int wm = w >> 2, wn = w & 3;          // 4 m-warps (80 rows) x 4 n-warps (16 cols)
    const int miN = (wm == 3) ? 3 : 5;          // wm=3 covers 240..319; skip >=288

    // Load W once (fp16), swizzled [m][k]: row = 256B, 16 uint4/row.
    for (int i = tid; i < 5120; i += 512) {
        const int m = i >> 4, q = i & 15;
        const uint32_t off = m * 256 + ((q * 16) ^ ((m & 7) * 16));
        *(uint4*)(smem + OFF_W + off) = ((const uint4*)d_Wh)[i];
    }

    const int lr = (lane & 7) + ((lane >> 3) & 1) * 8;
    const int lc = (lane >> 4) * 8;

    // Register prefetch of first tile's X block (exactly 4 float4/thread).
    float4 xpre[4];
    const int t0 = blockIdx.x;
    {
        const int b = t0 >> 10, p0 = (t0 & 1023) << 6;
        const float* Xg = x + (size_t)b * Cd * HW + p0;
        #pragma unroll
        for (int j = 0; j < 4; j++) {
            const int i = tid + j * 512;
            xpre[j] = *(const float4*)(Xg + (size_t)(i >> 4) * HW + (i & 15) * 4);
        }
    }

    for (int t = t0; t < NTILE; t += NCTA) {
        const int b = t >> 10, p0 = (t & 1023) << 6;

        // Convert prefetched fp32 -> fp16 into X buffer (swizzled [k][n]).
        #pragma unroll
        for (int j = 0; j < 4; j++) {
            const float4 v = xpre[j];
            const int i = tid + j * 512;
            const int k = i >> 4, n0 = (i & 15) * 4;
            uint2 hp;
            const __half2 h01 = __floats2half2_rn(v.x, v.y);
            const __half2 h23 = __floats2half2_rn(v.z, v.w);
            hp.x = *(const uint32_t*)&h01; hp.y = *(const uint32_t*)&h23;
            const uint32_t off = k * 128 + ((n0 * 2) ^ ((k & 7) * 16));
            *(uint2*)(smem + OFF_X + off) = hp;
        }
        __syncthreads();

        // Prefetch next tile's X (overlaps with compute below).
        const int tn = t + NCTA;
        if (tn < NTILE) {
            const int bn_ = tn >> 10, pn = (tn & 1023) << 6;
            const float* Xg = x + (size_t)bn_ * Cd * HW + pn;
            #pragma unroll
            for (int j = 0; j < 4; j++) {
                const int i = tid + j * 512;
                xpre[j] = *(const float4*)(Xg + (size_t)(i >> 4) * HW + (i & 15) * 4);
            }
        }

        // Compute: K loop over 8 chunks of 16.
        float acc[5][2][4] = {};
        #pragma unroll 1
        for (int kk = 0; kk < 8; kk++) {
            const int k0 = kk * 16;
            uint32_t ah[5][4];
            #pragma unroll
            for (int mi = 0; mi < 5; mi++) {
                if (mi >= miN) break;
                const int row = wm * 80 + mi * 16 + lr;
                const int col = k0 + lc;
                const uint32_t off = row * 256 + ((col * 2) ^ ((row & 7) * 16));
                ldsm_x4(ah[mi], sb + OFF_W + off);
            }
            uint32_t bh[4];
            {
                const int kr = k0 + lr;
                const int nc = wn * 16 + lc;
                const uint32_t off = kr * 128 + ((nc * 2) ^ ((kr & 7) * 16));
                ldsm_x4_t(bh, sb + OFF_X + off);
            }
            #pragma unroll
            for (int mi = 0; mi < 5; mi++) {
                if (mi >= miN) break;
                mma_f16(acc[mi][0], ah[mi], &bh[0]);
                mma_f16(acc[mi][1], ah[mi], &bh[2]);
            }
        }
        __syncthreads();   // all reads of X done; reuse region for epilogue

        // Epilogue: stage all 288 rows (stride 144B), then coalesced row stores.
        __half* Gout = d_G + (size_t)b * GR * HW;
        const int ccol = wn * 16 + (lane & 3) * 2;
        #pragma unroll
        for (int mi = 0; mi < 5; mi++) {
            const int mb = wm * 80 + mi * 16;
            if (mb >= GUSE || mi >= miN) break;
            const int idx0 = mb + (lane >> 2);
            #pragma unroll
            for (int ni = 0; ni < 2; ni++) {
                const uint32_t a0 = OFF_X + idx0 * EPSTRIDE + (ccol + ni * 8) * 2;
                *(__half2*)(smem + a0) =
                    __floats2half2_rn(acc[mi][ni][0], acc[mi][ni][1]);
                *(__half2*)(smem + a0 + 8 * EPSTRIDE) =
                    __floats2half2_rn(acc[mi][ni][2], acc[mi][ni][3]);
            }
        }
        __syncthreads();
        #pragma unroll
        for (int j = 0; j < 18; j++) {
            const int idx = w * 18 + j;            // 16*18 = 288 rows
            const uint32_t word = *(const uint32_t*)(smem + OFF_X + idx * EPSTRIDE + lane * 4);
            *(uint32_t*)((__half*)Gout + (size_t)idx * HW + p0 + lane * 2) = word;
        }
        __syncthreads();   // staged data consumed before next tile's convert
    }
}

// ---------------------------------------------------------------------------
// Combine: 64-pixel blocks, half2 loads (full-sector). Gates: 256 threads =
// 4 dirs x 64 px. Aggregation: 8 warps x 16 channels, lane = pixel pair.
// Partial GN sums + fused last-block finalize. Deterministic.
// ---------------------------------------------------------------------------
__global__ void __launch_bounds__(256) combine_kernel(const float* __restrict__ ba1,
                                                      const float* __restrict__ Wa2,
                                                      const float* __restrict__ ba2) {
    const int blk = blockIdx.x;            // 0..2047
    const int b   = blk >> 10;
    const int p0  = (blk & 1023) << 6;     // 64-px tile, single image row
    const __half* __restrict__ G = d_G + (size_t)b * GR * HW;
    __half* __restrict__ nn = d_nn + (size_t)b * Cd * HW;

    __shared__ float a_s[4][64];
    __shared__ float cA_s[128], cB_s[128];
    __shared__ float reds[8], redq[8];

    const int tid = threadIdx.x;
    if (tid < 128) { cA_s[tid] = d_cA[tid]; cB_s[tid] = d_cB[tid]; }

    const int hrow = p0 >> 8;

    {   // gates: one per thread (dir, px)
        const int dir = tid >> 6, px = tid & 63;
        const int p = p0 + px, wcol = p & 255;
        int off; bool valid;
        switch (dir) {
            case 0:  off = -256; valid = (hrow > 0);    break;
            case 1:  off =  256; valid = (hrow < 255);  break;
            case 2:  off =   -1; valid = (wcol > 0);    break;
            default: off =    1; valid = (wcol < 255);  break;
        }
        float a = 0.f;
        if (valid) {
            float logit = ba2[0];
            const __half* Gu = G + 256 * HW + p;
            const __half* Gt = G + 272 * HW + p + off;
            #pragma unroll
            for (int i = 0; i < 16; i++) {
                float hv = __half2float(Gu[i * HW]) + __half2float(Gt[i * HW]) + ba1[i];
                hv = hv > 0.f ? hv : 0.2f * hv;
                logit += Wa2[i] * hv;
            }
            a = 1.f / (1.f + expf(-logit));
        }
        a_s[dir][px] = a;
    }
    __syncthreads();

    const int wq = tid >> 5, lane = tid & 31;
    const int q = p0 + 2 * lane;            // even pixel of pair
    const int px2 = 2 * lane;
    const float au0 = a_s[0][px2], au1 = a_s[0][px2 + 1];
    const float ad0 = a_s[1][px2], ad1 = a_s[1][px2 + 1];
    const float al0 = a_s[2][px2], al1 = a_s[2][px2 + 1];
    const float ar0 = a_s[3][px2], ar1 = a_s[3][px2 + 1];

    float lsum = 0.f, lsq = 0.f;
    #pragma unroll
    for (int ci = 0; ci < 16; ci++) {
        const int c = (wq << 4) + ci;
        const __half* z = G + (size_t)c * HW;
        const __half* y = G + (size_t)(128 + c) * HW;
        const float cb = cB_s[c];
        const float2 zv = __half22float2(*(const __half2*)(z + q));
        const float2 yu = __half22float2(*(const __half2*)(y + q - 256));
        const float2 yd = __half22float2(*(const __half2*)(y + q + 256));
        const float2 ym = __half22float2(*(const __half2*)(y + q));       // y[q], y[q+1]
        const float2 yl = __half22float2(*(const __half2*)(y + q - 2));   // y[q-2], y[q-1]
        const float2 yr = __half22float2(*(const __half2*)(y + q + 2));   // y[q+2], y[q+3]
        float v0 = zv.x + cA_s[c]
                 + au0 * (yu.x + cb) + ad0 * (yd.x + cb)
                 + al0 * (yl.y + cb) + ar0 * (ym.y + cb);
        float v1 = zv.y + cA_s[c]
                 + au1 * (yu.y + cb) + ad1 * (yd.y + cb)
                 + al1 * (ym.x + cb) + ar1 * (yr.x + cb);
        const __half2 hv = __floats2half2_rn(v0, v1);
        *(__half2*)(nn + (size_t)c * HW + q) = hv;
        const float2 vr = __half22float2(hv);   // stats from stored (rounded) values
        lsum += vr.x + vr.y;
        lsq  += vr.x * vr.x + vr.y * vr.y;
    }

    // Deterministic butterfly + fixed-order cross-warp reduction.
    #pragma unroll
    for (int s = 16; s > 0; s >>= 1) {
        lsum += __shfl_xor_sync(0xFFFFFFFFu, lsum, s);
        lsq  += __shfl_xor_sync(0xFFFFFFFFu, lsq,  s);
    }
    if (lane == 0) { reds[wq] = lsum; redq[wq] = lsq; }
    __syncthreads();
    if (tid == 0) {
        float s = 0.f, qv = 0.f;
        #pragma unroll
        for (int i = 0; i < 8; i++) { s += reds[i]; qv += redq[i]; }
        d_part[blk * 2] = (double)s;
        d_part[blk * 2 + 1] = (double)qv;
    }

    // Last-block GroupNorm finalize (threadfence-reduction pattern).
    __shared__ unsigned isLast;
    __threadfence();
    if (tid == 0) isLast = (atomicAdd(&d_count, 1u) == 2047u) ? 1u : 0u;
    __syncthreads();
    if (isLast) {
        __threadfence();
        __shared__ double rs[256], rq[256];
        for (int bb = 0; bb < Bd; bb++) {
            double s = 0.0, qd = 0.0;
            for (int i = tid; i < 1024; i += 256) {
                s  += d_part[(bb * 1024 + i) * 2];
                qd += d_part[(bb * 1024 + i) * 2 + 1];
            }
            rs[tid] = s; rq[tid] = qd; __syncthreads();
            for (int st = 128; st > 0; st >>= 1) {
                if (tid < st) { rs[tid] += rs[tid + st]; rq[tid] += rq[tid + st]; }
                __syncthreads();
            }
            if (tid == 0) {
                const double N = (double)Cd * HW;
                const double mu = rs[0] / N;
                const double var = rq[0] / N - mu * mu;
                d_stats[bb * 2]     = (float)mu;
                d_stats[bb * 2 + 1] = (float)rsqrt(var + EPSV);
            }
            __syncthreads();
        }
        if (tid == 0) d_count = 0;   // self-reset for next graph replay
    }
}

// ---------------------------------------------------------------------------
// Epilogue: out = relu((nn - mu)*rsig*gamma + beta) + x   (nn is fp16)
// ---------------------------------------------------------------------------
__global__ void __launch_bounds__(256) final_kernel(const float* __restrict__ x,
                                                    const float* __restrict__ gamma,
                                                    const float* __restrict__ beta,
                                                    float* __restrict__ out) {
    const int idx4 = blockIdx.x * blockDim.x + threadIdx.x;
    const int b = idx4 >> 21;
    const int c = (idx4 >> 14) & 127;
    const float mu = d_stats[b * 2], rs = d_stats[b * 2 + 1];
    const float g  = gamma[c] * rs;
    const float bt = beta[c] - mu * g;
    const uint2 hv = ((const uint2*)d_nn)[idx4];
    const float2 v01 = __half22float2(*(const __half2*)&hv.x);
    const float2 v23 = __half22float2(*(const __half2*)&hv.y);
    const float4 xv = ((const float4*)x)[idx4];
    float4 o;
    o.x = fmaxf(v01.x * g + bt, 0.f) + xv.x;
    o.y = fmaxf(v01.y * g + bt, 0.f) + xv.y;
    o.z = fmaxf(v23.x * g + bt, 0.f) + xv.z;
    o.w = fmaxf(v23.y * g + bt, 0.f) + xv.w;
    ((float4*)out)[idx4] = o;
}

// ---------------------------------------------------------------------------
// Launch
// ---------------------------------------------------------------------------
extern "C" void kernel_launch(void* const* d_in, const int* in_sizes, int n_in,
                              void* d_out, int out_size) {
    const float* x     = (const float*)d_in[0];
    const float* Wn    = (const float*)d_in[1];
    const float* bn    = (const float*)d_in[2];
    const float* We    = (const float*)d_in[3];
    const float* be    = (const float*)d_in[4];
    const float* Wa1   = (const float*)d_in[5];
    const float* ba1   = (const float*)d_in[6];
    const float* Wa2   = (const float*)d_in[7];
    const float* ba2   = (const float*)d_in[8];
    const float* Wu    = (const float*)d_in[9];
    const float* bu    = (const float*)d_in[10];
    const float* gamma = (const float*)d_in[11];
    const float* beta  = (const float*)d_in[12];
    float* out = (float*)d_out;

    cudaFuncSetAttribute(mma_kernel, cudaFuncAttributeMaxDynamicSharedMemorySize, SMEM_SZ);

    prep_kernel<<<GR + 1, 128>>>(Wn, We, Wa1, Wu, bn, be, bu);
    mma_kernel<<<NCTA, 512, SMEM_SZ>>>(x);
    combine_kernel<<<2048, 256>>>(ba1, Wa2, ba2);
    final_kernel<<<(Bd * Cd * HW / 4) / 256, 256>>>(x, gamma, beta, out);
}